// round 1
// baseline (speedup 1.0000x reference)
#include <cuda_runtime.h>
#include <math.h>

#define B_   8
#define H_   16
#define L_   512
#define DIM_ 1024
#define HD_  64

// Scratch (device globals: allocation-free per harness rules)
__device__ float g_Q [B_ * L_ * DIM_];        // 16 MB  (b*L+i, h*64+d)
__device__ float g_K [B_ * L_ * DIM_];        // 16 MB
__device__ float g_V [B_ * L_ * DIM_];        // 16 MB
__device__ float g_AO[B_ * L_ * DIM_];        // 16 MB  attention output, (b,i,dim) layout
__device__ float g_S [B_ * H_ * L_ * L_];     // 134 MB scores -> mixed attn (in-place)

// ---------------------------------------------------------------------------
// SGEMM: C[M,N] = A[M,K] @ W[N,K]^T + bias[N]
// BM=BN=128, BK=8, 256 threads, 8x8 register tile per thread.
// a_sel: 0 -> use A arg, 1 -> A = g_AO
// c_sel: 0->g_Q, 1->g_K, 2->g_V, 3 -> use C arg (d_out)
// ---------------------------------------------------------------------------
__global__ __launch_bounds__(256) void sgemm_bias_kernel(
    const float* __restrict__ A_ext, int a_sel,
    const float* __restrict__ W,
    const float* __restrict__ bias,
    float* __restrict__ C_ext, int c_sel,
    int M, int N, int K)
{
    const float* A = (a_sel == 0) ? A_ext : (const float*)g_AO;
    float* C = (c_sel == 0) ? g_Q : (c_sel == 1) ? g_K : (c_sel == 2) ? g_V : C_ext;

    __shared__ float As[8 * 128];
    __shared__ float Ws[8 * 128];

    const int tid  = threadIdx.x;
    const int tCol = tid & 15;        // 0..15
    const int tRow = tid >> 4;        // 0..15
    const float* Ab = A + (size_t)blockIdx.y * 128 * K;
    const float* Wb = W + (size_t)blockIdx.x * 128 * K;
    const int lr = tid >> 1;          // 0..127 row within tile
    const int lc = (tid & 1) * 4;     // k offset 0 or 4

    float acc[8][8];
#pragma unroll
    for (int i = 0; i < 8; i++)
#pragma unroll
        for (int j = 0; j < 8; j++) acc[i][j] = 0.f;

    for (int k0 = 0; k0 < K; k0 += 8) {
        float4 a4 = *reinterpret_cast<const float4*>(Ab + (size_t)lr * K + k0 + lc);
        float4 w4 = *reinterpret_cast<const float4*>(Wb + (size_t)lr * K + k0 + lc);
        As[(lc + 0) * 128 + lr] = a4.x;
        As[(lc + 1) * 128 + lr] = a4.y;
        As[(lc + 2) * 128 + lr] = a4.z;
        As[(lc + 3) * 128 + lr] = a4.w;
        Ws[(lc + 0) * 128 + lr] = w4.x;
        Ws[(lc + 1) * 128 + lr] = w4.y;
        Ws[(lc + 2) * 128 + lr] = w4.z;
        Ws[(lc + 3) * 128 + lr] = w4.w;
        __syncthreads();
#pragma unroll
        for (int k = 0; k < 8; k++) {
            float rm[8], rn[8];
#pragma unroll
            for (int i = 0; i < 8; i++) rm[i] = As[k * 128 + tRow * 8 + i];
#pragma unroll
            for (int j = 0; j < 8; j++) rn[j] = Ws[k * 128 + tCol * 8 + j];
#pragma unroll
            for (int i = 0; i < 8; i++)
#pragma unroll
                for (int j = 0; j < 8; j++)
                    acc[i][j] = fmaf(rm[i], rn[j], acc[i][j]);
        }
        __syncthreads();
    }

#pragma unroll
    for (int i = 0; i < 8; i++) {
        int m = blockIdx.y * 128 + tRow * 8 + i;
#pragma unroll
        for (int j = 0; j < 8; j += 4) {
            int n = blockIdx.x * 128 + tCol * 8 + j;
            float4 o;
            o.x = acc[i][j + 0] + bias[n + 0];
            o.y = acc[i][j + 1] + bias[n + 1];
            o.z = acc[i][j + 2] + bias[n + 2];
            o.w = acc[i][j + 3] + bias[n + 3];
            *reinterpret_cast<float4*>(C + (size_t)m * N + n) = o;
        }
    }
}

// ---------------------------------------------------------------------------
// Batched QK^T: S[bh,i,j] = (1/8) * sum_d Q[bh,i,d]*K[bh,j,d]
// 64x64 output tile per block, 256 threads, 4x4 micro-tile (strided by 16).
// ---------------------------------------------------------------------------
__global__ __launch_bounds__(256) void qk_kernel()
{
    const int bh = blockIdx.z;
    const int b = bh >> 4;
    const int h = bh & 15;
    const int i0 = blockIdx.y * 64;
    const int j0 = blockIdx.x * 64;

    __shared__ float Qs[64][68];
    __shared__ float Ks[64][68];

    const int tid = threadIdx.x;
#pragma unroll
    for (int t = 0; t < 4; t++) {
        int f  = tid + t * 256;           // 0..1023
        int r  = f >> 4;                  // 0..63
        int d4 = (f & 15) * 4;            // 0..60
        *reinterpret_cast<float4*>(&Qs[r][d4]) =
            *reinterpret_cast<const float4*>(&g_Q[(size_t)(b * L_ + i0 + r) * DIM_ + h * HD_ + d4]);
        *reinterpret_cast<float4*>(&Ks[r][d4]) =
            *reinterpret_cast<const float4*>(&g_K[(size_t)(b * L_ + j0 + r) * DIM_ + h * HD_ + d4]);
    }
    __syncthreads();

    const int tRow = tid >> 4;
    const int tCol = tid & 15;
    float acc[4][4];
#pragma unroll
    for (int a = 0; a < 4; a++)
#pragma unroll
        for (int c = 0; c < 4; c++) acc[a][c] = 0.f;

#pragma unroll 4
    for (int d = 0; d < 64; d++) {
        float qv[4], kv[4];
#pragma unroll
        for (int t = 0; t < 4; t++) {
            qv[t] = Qs[tRow + 16 * t][d];
            kv[t] = Ks[tCol + 16 * t][d];
        }
#pragma unroll
        for (int a = 0; a < 4; a++)
#pragma unroll
            for (int c = 0; c < 4; c++)
                acc[a][c] = fmaf(qv[a], kv[c], acc[a][c]);
    }

#pragma unroll
    for (int a = 0; a < 4; a++) {
        int i = i0 + tRow + 16 * a;
        float* Sr = g_S + ((size_t)bh * L_ + i) * L_;
#pragma unroll
        for (int c = 0; c < 4; c++) {
            int j = j0 + tCol + 16 * c;
            Sr[j] = acc[a][c] * 0.125f;   // 1/sqrt(64)
        }
    }
}

// ---------------------------------------------------------------------------
// Dual softmax + Atchley bias + mix (in place on g_S).
// One block (128 threads) per (bh, i) row; 4 columns per thread.
// attn = (1-r)*softmax(std) + r*softmax(bio), r = (tanh(mix)+1)/2
// bio[j] = sum_q (sum_p atc1[b,i,p]*U[h,p,q]) * atc2[b,j,q]
// ---------------------------------------------------------------------------
__global__ __launch_bounds__(128) void softmax_mix_kernel(
    const float* __restrict__ atc1, const float* __restrict__ atc2,
    const float* __restrict__ U, const float* __restrict__ mixp)
{
    const int row = blockIdx.x;         // 0 .. B*H*L-1
    const int bh = row >> 9;
    const int i  = row & 511;
    const int b  = bh >> 4;
    const int h  = bh & 15;
    const int tid = threadIdx.x;

    float a1u[5];
    {
        float a1[5];
#pragma unroll
        for (int p = 0; p < 5; p++) a1[p] = __ldg(&atc1[(size_t)(b * L_ + i) * 5 + p]);
#pragma unroll
        for (int q = 0; q < 5; q++) {
            float s = 0.f;
#pragma unroll
            for (int p = 0; p < 5; p++) s = fmaf(a1[p], __ldg(&U[h * 25 + p * 5 + q]), s);
            a1u[q] = s;
        }
    }

    float* Srow = g_S + (size_t)row * L_;
    float sv[4], bv[4];
#pragma unroll
    for (int t = 0; t < 4; t++) {
        int j = tid + t * 128;
        sv[t] = Srow[j];
        const float* a2 = atc2 + (size_t)(b * L_ + j) * 5;
        float s = 0.f;
#pragma unroll
        for (int q = 0; q < 5; q++) s = fmaf(a1u[q], __ldg(&a2[q]), s);
        bv[t] = s;
    }

    __shared__ float red1[4], red2[4];
    const int wid = tid >> 5, lane = tid & 31;

    // max reduce (both)
    float m1 = fmaxf(fmaxf(sv[0], sv[1]), fmaxf(sv[2], sv[3]));
    float m2 = fmaxf(fmaxf(bv[0], bv[1]), fmaxf(bv[2], bv[3]));
#pragma unroll
    for (int o = 16; o; o >>= 1) {
        m1 = fmaxf(m1, __shfl_xor_sync(0xffffffffu, m1, o));
        m2 = fmaxf(m2, __shfl_xor_sync(0xffffffffu, m2, o));
    }
    if (lane == 0) { red1[wid] = m1; red2[wid] = m2; }
    __syncthreads();
    m1 = fmaxf(fmaxf(red1[0], red1[1]), fmaxf(red1[2], red1[3]));
    m2 = fmaxf(fmaxf(red2[0], red2[1]), fmaxf(red2[2], red2[3]));

    // sum reduce (both)
    float l1 = 0.f, l2 = 0.f;
#pragma unroll
    for (int t = 0; t < 4; t++) {
        l1 += __expf(sv[t] - m1);
        l2 += __expf(bv[t] - m2);
    }
#pragma unroll
    for (int o = 16; o; o >>= 1) {
        l1 += __shfl_xor_sync(0xffffffffu, l1, o);
        l2 += __shfl_xor_sync(0xffffffffu, l2, o);
    }
    __syncthreads();                    // protect red reuse
    if (lane == 0) { red1[wid] = l1; red2[wid] = l2; }
    __syncthreads();
    l1 = red1[0] + red1[1] + red1[2] + red1[3];
    l2 = red2[0] + red2[1] + red2[2] + red2[3];

    const float mp = __ldg(mixp);
    const float rr = (tanhf(mp) + 1.f) * 0.5f;
    const float c1 = (1.f - rr) / l1;
    const float c2 = rr / l2;
#pragma unroll
    for (int t = 0; t < 4; t++) {
        int j = tid + t * 128;
        Srow[j] = c1 * __expf(sv[t] - m1) + c2 * __expf(bv[t] - m2);
    }
}

// ---------------------------------------------------------------------------
// Batched PV: AO[b,i, h*64+d] = sum_j attn[bh,i,j] * V[bh,j,d]
// Block per (bh, i-tile of 64). 256 threads, 4x4 micro-tile.
// ---------------------------------------------------------------------------
__global__ __launch_bounds__(256) void pv_kernel()
{
    const int bh = blockIdx.y;
    const int b = bh >> 4;
    const int h = bh & 15;
    const int i0 = blockIdx.x * 64;

    __shared__ float Ps[64][68];
    __shared__ float Vs[64][68];

    const int tid = threadIdx.x;
    const int tRow = tid >> 4;
    const int tCol = tid & 15;

    float acc[4][4];
#pragma unroll
    for (int a = 0; a < 4; a++)
#pragma unroll
        for (int c = 0; c < 4; c++) acc[a][c] = 0.f;

    for (int j0 = 0; j0 < L_; j0 += 64) {
#pragma unroll
        for (int t = 0; t < 4; t++) {
            int f  = tid + t * 256;
            int r  = f >> 4;
            int c4 = (f & 15) * 4;
            *reinterpret_cast<float4*>(&Ps[r][c4]) =
                *reinterpret_cast<const float4*>(&g_S[((size_t)bh * L_ + i0 + r) * L_ + j0 + c4]);
            *reinterpret_cast<float4*>(&Vs[r][c4]) =
                *reinterpret_cast<const float4*>(&g_V[(size_t)(b * L_ + j0 + r) * DIM_ + h * HD_ + c4]);
        }
        __syncthreads();
#pragma unroll 4
        for (int j = 0; j < 64; j++) {
            float pv[4], vv[4];
#pragma unroll
            for (int t = 0; t < 4; t++) {
                pv[t] = Ps[tRow + 16 * t][j];
                vv[t] = Vs[j][tCol + 16 * t];
            }
#pragma unroll
            for (int a = 0; a < 4; a++)
#pragma unroll
                for (int c = 0; c < 4; c++)
                    acc[a][c] = fmaf(pv[a], vv[c], acc[a][c]);
        }
        __syncthreads();
    }

#pragma unroll
    for (int a = 0; a < 4; a++) {
        int i = i0 + tRow + 16 * a;
#pragma unroll
        for (int c = 0; c < 4; c++) {
            int d = tCol + 16 * c;
            g_AO[(size_t)(b * L_ + i) * DIM_ + h * HD_ + d] = acc[a][c];
        }
    }
}

// ---------------------------------------------------------------------------
extern "C" void kernel_launch(void* const* d_in, const int* in_sizes, int n_in,
                              void* d_out, int out_size)
{
    const float* seq1 = (const float*)d_in[0];
    const float* seq2 = (const float*)d_in[1];
    const float* atc1 = (const float*)d_in[2];
    const float* atc2 = (const float*)d_in[3];
    const float* Wq   = (const float*)d_in[4];
    const float* bq   = (const float*)d_in[5];
    const float* Wk   = (const float*)d_in[6];
    const float* bk   = (const float*)d_in[7];
    const float* Wv   = (const float*)d_in[8];
    const float* bv   = (const float*)d_in[9];
    const float* Wo   = (const float*)d_in[10];
    const float* bo   = (const float*)d_in[11];
    const float* U    = (const float*)d_in[12];
    const float* mixp = (const float*)d_in[13];
    float* out = (float*)d_out;

    const int M = B_ * L_;   // 4096
    dim3 gproj(DIM_ / 128, M / 128);   // (8, 32)

    // Projections -> g_Q / g_K / g_V
    sgemm_bias_kernel<<<gproj, 256>>>(seq1, 0, Wq, bq, nullptr, 0, M, DIM_, DIM_);
    sgemm_bias_kernel<<<gproj, 256>>>(seq2, 0, Wk, bk, nullptr, 1, M, DIM_, DIM_);
    sgemm_bias_kernel<<<gproj, 256>>>(seq2, 0, Wv, bv, nullptr, 2, M, DIM_, DIM_);

    // Scores
    qk_kernel<<<dim3(L_ / 64, L_ / 64, B_ * H_), 256>>>();

    // Dual softmax + bio bias + mix (in place)
    softmax_mix_kernel<<<B_ * H_ * L_, 128>>>(atc1, atc2, U, mixp);

    // attn @ V  -> g_AO in (b, i, dim) layout
    pv_kernel<<<dim3(L_ / 64, B_ * H_), 256>>>();

    // Output projection -> d_out
    sgemm_bias_kernel<<<gproj, 256>>>(nullptr, 1, Wo, bo, out, 3, M, DIM_, DIM_);
}

// round 3
// speedup vs baseline: 1.9228x; 1.9228x over previous
#include <cuda_runtime.h>
#include <math.h>
#include <cstdint>

#define B_   8
#define H_   16
#define L_   512
#define DIM_ 1024
#define HD_  64

// Scratch (device globals: allocation-free per harness rules)
__device__ float g_Q [B_ * L_ * DIM_];
__device__ float g_K [B_ * L_ * DIM_];
__device__ float g_V [B_ * L_ * DIM_];
__device__ float g_AO[B_ * L_ * DIM_];
__device__ float g_S [B_ * H_ * L_ * L_];     // 134 MB scores -> mixed attn

// ===========================================================================
// tf32 helpers (baseline PTX, supported on compute_103)
// ===========================================================================
__device__ __forceinline__ uint32_t f2tf32(float f) {
    uint32_t o;
    asm("cvt.rna.tf32.f32 %0, %1;" : "=r"(o) : "f"(f));
    return o;
}

__device__ __forceinline__ void mma_tf32(
    float& d0, float& d1, float& d2, float& d3,
    uint32_t a0, uint32_t a1, uint32_t a2, uint32_t a3,
    uint32_t b0, uint32_t b1)
{
    asm volatile(
        "mma.sync.aligned.m16n8k8.row.col.f32.tf32.tf32.f32 "
        "{%0,%1,%2,%3}, {%4,%5,%6,%7}, {%8,%9}, {%0,%1,%2,%3};"
        : "+f"(d0), "+f"(d1), "+f"(d2), "+f"(d3)
        : "r"(a0), "r"(a1), "r"(a2), "r"(a3), "r"(b0), "r"(b1));
}

// ===========================================================================
// tf32 mma.sync GEMM:  C[M,1024] = A[M,1024] @ W[1024,1024]^T + bias
// CTA tile 128x128, 8 warps (4m x 2n), warp tile 32x64.
// K-chunk 16, double-buffered SMEM, stride-20 padding (conflict-free frags).
// a_sel: 0 -> use A arg, 1 -> A = g_AO
// c_sel: 0->g_Q, 1->g_K, 2->g_V, 3 -> use C arg (d_out)
// ===========================================================================
#define GK    1024
#define KB    16
#define NCH   (GK / KB)      // 64
#define SST   20             // smem row stride in words (bank-conflict-free)

__global__ __launch_bounds__(256, 2) void gemm_tf32_mma(
    const float* __restrict__ A_ext, int a_sel,
    const float* __restrict__ W,
    const float* __restrict__ bias,
    float* __restrict__ C_ext, int c_sel)
{
    const float* A = (a_sel == 0) ? A_ext : (const float*)g_AO;
    float* C = (c_sel == 0) ? g_Q : (c_sel == 1) ? g_K : (c_sel == 2) ? g_V : C_ext;

    __shared__ uint32_t As[2][128 * SST];
    __shared__ uint32_t Bs[2][128 * SST];
    __shared__ float s_bias[128];

    const int tid  = threadIdx.x;
    const int wid  = tid >> 5;
    const int lane = tid & 31;
    const int g    = lane >> 2;      // group 0..7
    const int tg   = lane & 3;       // thread in group 0..3
    const int mrow = (wid >> 1) * 32;
    const int ncol = (wid & 1) * 64;

    const float* Arow = A + (size_t)blockIdx.y * 128 * GK;
    const float* Wrow = W + (size_t)blockIdx.x * 128 * GK;

    if (tid < 128) s_bias[tid] = bias[blockIdx.x * 128 + tid];

    // global-load slots: 512 float4 per tile, 2 per thread
    const int s0 = tid, s1 = tid + 256;
    const int r0 = s0 >> 2, k40 = (s0 & 3) << 2;
    const int r1 = s1 >> 2, k41 = (s1 & 3) << 2;

    float acc[2][8][4];
#pragma unroll
    for (int mt = 0; mt < 2; mt++)
#pragma unroll
        for (int nt = 0; nt < 8; nt++)
#pragma unroll
            for (int e = 0; e < 4; e++) acc[mt][nt][e] = 0.f;

    // Prologue: chunk 0 -> stage 0
    {
        float4 va0 = __ldg((const float4*)(Arow + (size_t)r0 * GK + k40));
        float4 va1 = __ldg((const float4*)(Arow + (size_t)r1 * GK + k41));
        float4 vb0 = __ldg((const float4*)(Wrow + (size_t)r0 * GK + k40));
        float4 vb1 = __ldg((const float4*)(Wrow + (size_t)r1 * GK + k41));
        uint4 u;
        u.x = f2tf32(va0.x); u.y = f2tf32(va0.y); u.z = f2tf32(va0.z); u.w = f2tf32(va0.w);
        *(uint4*)&As[0][r0 * SST + k40] = u;
        u.x = f2tf32(va1.x); u.y = f2tf32(va1.y); u.z = f2tf32(va1.z); u.w = f2tf32(va1.w);
        *(uint4*)&As[0][r1 * SST + k41] = u;
        u.x = f2tf32(vb0.x); u.y = f2tf32(vb0.y); u.z = f2tf32(vb0.z); u.w = f2tf32(vb0.w);
        *(uint4*)&Bs[0][r0 * SST + k40] = u;
        u.x = f2tf32(vb1.x); u.y = f2tf32(vb1.y); u.z = f2tf32(vb1.z); u.w = f2tf32(vb1.w);
        *(uint4*)&Bs[0][r1 * SST + k41] = u;
    }
    __syncthreads();

    for (int i = 0; i < NCH; i++) {
        const int st = i & 1;
        float4 va0, va1, vb0, vb1;
        const bool more = (i + 1 < NCH);
        if (more) {
            const int ko = (i + 1) * KB;
            va0 = __ldg((const float4*)(Arow + (size_t)r0 * GK + ko + k40));
            va1 = __ldg((const float4*)(Arow + (size_t)r1 * GK + ko + k41));
            vb0 = __ldg((const float4*)(Wrow + (size_t)r0 * GK + ko + k40));
            vb1 = __ldg((const float4*)(Wrow + (size_t)r1 * GK + ko + k41));
        }

        // compute on stage st: 2 ksteps of 8
#pragma unroll
        for (int ks = 0; ks < 2; ks++) {
            uint32_t a[2][4];
#pragma unroll
            for (int mt = 0; mt < 2; mt++) {
                const int rb = mrow + mt * 16 + g;
                a[mt][0] = As[st][(rb)     * SST + ks * 8 + tg];
                a[mt][1] = As[st][(rb + 8) * SST + ks * 8 + tg];
                a[mt][2] = As[st][(rb)     * SST + ks * 8 + tg + 4];
                a[mt][3] = As[st][(rb + 8) * SST + ks * 8 + tg + 4];
            }
#pragma unroll
            for (int nt = 0; nt < 8; nt++) {
                const int rw = ncol + nt * 8 + g;
                uint32_t b0 = Bs[st][rw * SST + ks * 8 + tg];
                uint32_t b1 = Bs[st][rw * SST + ks * 8 + tg + 4];
#pragma unroll
                for (int mt = 0; mt < 2; mt++)
                    mma_tf32(acc[mt][nt][0], acc[mt][nt][1], acc[mt][nt][2], acc[mt][nt][3],
                             a[mt][0], a[mt][1], a[mt][2], a[mt][3], b0, b1);
            }
        }

        if (more) {
            const int ns = st ^ 1;
            uint4 u;
            u.x = f2tf32(va0.x); u.y = f2tf32(va0.y); u.z = f2tf32(va0.z); u.w = f2tf32(va0.w);
            *(uint4*)&As[ns][r0 * SST + k40] = u;
            u.x = f2tf32(va1.x); u.y = f2tf32(va1.y); u.z = f2tf32(va1.z); u.w = f2tf32(va1.w);
            *(uint4*)&As[ns][r1 * SST + k41] = u;
            u.x = f2tf32(vb0.x); u.y = f2tf32(vb0.y); u.z = f2tf32(vb0.z); u.w = f2tf32(vb0.w);
            *(uint4*)&Bs[ns][r0 * SST + k40] = u;
            u.x = f2tf32(vb1.x); u.y = f2tf32(vb1.y); u.z = f2tf32(vb1.z); u.w = f2tf32(vb1.w);
            *(uint4*)&Bs[ns][r1 * SST + k41] = u;
            __syncthreads();
        }
    }

    // Epilogue: each mma D tile: d0/d1 at (row g, col 2*tg(+1)), d2/d3 at row g+8
#pragma unroll
    for (int mt = 0; mt < 2; mt++) {
#pragma unroll
        for (int nt = 0; nt < 8; nt++) {
            const int row = mrow + mt * 16 + g;
            const int col = ncol + nt * 8 + 2 * tg;
            const int gm0 = blockIdx.y * 128 + row;
            const int gc  = blockIdx.x * 128 + col;
            float2 o;
            o.x = acc[mt][nt][0] + s_bias[col];
            o.y = acc[mt][nt][1] + s_bias[col + 1];
            *(float2*)(C + (size_t)gm0 * DIM_ + gc) = o;
            o.x = acc[mt][nt][2] + s_bias[col];
            o.y = acc[mt][nt][3] + s_bias[col + 1];
            *(float2*)(C + (size_t)(gm0 + 8) * DIM_ + gc) = o;
        }
    }
}

// ---------------------------------------------------------------------------
// Batched QK^T (unchanged, known-passing)
// ---------------------------------------------------------------------------
__global__ __launch_bounds__(256) void qk_kernel()
{
    const int bh = blockIdx.z;
    const int b = bh >> 4;
    const int h = bh & 15;
    const int i0 = blockIdx.y * 64;
    const int j0 = blockIdx.x * 64;

    __shared__ float Qs[64][68];
    __shared__ float Ks[64][68];

    const int tid = threadIdx.x;
#pragma unroll
    for (int t = 0; t < 4; t++) {
        int f  = tid + t * 256;
        int r  = f >> 4;
        int d4 = (f & 15) * 4;
        *reinterpret_cast<float4*>(&Qs[r][d4]) =
            *reinterpret_cast<const float4*>(&g_Q[(size_t)(b * L_ + i0 + r) * DIM_ + h * HD_ + d4]);
        *reinterpret_cast<float4*>(&Ks[r][d4]) =
            *reinterpret_cast<const float4*>(&g_K[(size_t)(b * L_ + j0 + r) * DIM_ + h * HD_ + d4]);
    }
    __syncthreads();

    const int tRow = tid >> 4;
    const int tCol = tid & 15;
    float acc[4][4];
#pragma unroll
    for (int a = 0; a < 4; a++)
#pragma unroll
        for (int c = 0; c < 4; c++) acc[a][c] = 0.f;

#pragma unroll 4
    for (int d = 0; d < 64; d++) {
        float qv[4], kv[4];
#pragma unroll
        for (int t = 0; t < 4; t++) {
            qv[t] = Qs[tRow + 16 * t][d];
            kv[t] = Ks[tCol + 16 * t][d];
        }
#pragma unroll
        for (int a = 0; a < 4; a++)
#pragma unroll
            for (int c = 0; c < 4; c++)
                acc[a][c] = fmaf(qv[a], kv[c], acc[a][c]);
    }

#pragma unroll
    for (int a = 0; a < 4; a++) {
        int i = i0 + tRow + 16 * a;
        float* Sr = g_S + ((size_t)bh * L_ + i) * L_;
#pragma unroll
        for (int c = 0; c < 4; c++) {
            int j = j0 + tCol + 16 * c;
            Sr[j] = acc[a][c] * 0.125f;
        }
    }
}

// ---------------------------------------------------------------------------
// Dual softmax + Atchley bias + mix (unchanged)
// ---------------------------------------------------------------------------
__global__ __launch_bounds__(128) void softmax_mix_kernel(
    const float* __restrict__ atc1, const float* __restrict__ atc2,
    const float* __restrict__ U, const float* __restrict__ mixp)
{
    const int row = blockIdx.x;
    const int bh = row >> 9;
    const int i  = row & 511;
    const int b  = bh >> 4;
    const int h  = bh & 15;
    const int tid = threadIdx.x;

    float a1u[5];
    {
        float a1[5];
#pragma unroll
        for (int p = 0; p < 5; p++) a1[p] = __ldg(&atc1[(size_t)(b * L_ + i) * 5 + p]);
#pragma unroll
        for (int q = 0; q < 5; q++) {
            float s = 0.f;
#pragma unroll
            for (int p = 0; p < 5; p++) s = fmaf(a1[p], __ldg(&U[h * 25 + p * 5 + q]), s);
            a1u[q] = s;
        }
    }

    float* Srow = g_S + (size_t)row * L_;
    float sv[4], bv[4];
#pragma unroll
    for (int t = 0; t < 4; t++) {
        int j = tid + t * 128;
        sv[t] = Srow[j];
        const float* a2 = atc2 + (size_t)(b * L_ + j) * 5;
        float s = 0.f;
#pragma unroll
        for (int q = 0; q < 5; q++) s = fmaf(a1u[q], __ldg(&a2[q]), s);
        bv[t] = s;
    }

    __shared__ float red1[4], red2[4];
    const int wid = tid >> 5, lane = tid & 31;

    float m1 = fmaxf(fmaxf(sv[0], sv[1]), fmaxf(sv[2], sv[3]));
    float m2 = fmaxf(fmaxf(bv[0], bv[1]), fmaxf(bv[2], bv[3]));
#pragma unroll
    for (int o = 16; o; o >>= 1) {
        m1 = fmaxf(m1, __shfl_xor_sync(0xffffffffu, m1, o));
        m2 = fmaxf(m2, __shfl_xor_sync(0xffffffffu, m2, o));
    }
    if (lane == 0) { red1[wid] = m1; red2[wid] = m2; }
    __syncthreads();
    m1 = fmaxf(fmaxf(red1[0], red1[1]), fmaxf(red1[2], red1[3]));
    m2 = fmaxf(fmaxf(red2[0], red2[1]), fmaxf(red2[2], red2[3]));

    float l1 = 0.f, l2 = 0.f;
#pragma unroll
    for (int t = 0; t < 4; t++) {
        l1 += __expf(sv[t] - m1);
        l2 += __expf(bv[t] - m2);
    }
#pragma unroll
    for (int o = 16; o; o >>= 1) {
        l1 += __shfl_xor_sync(0xffffffffu, l1, o);
        l2 += __shfl_xor_sync(0xffffffffu, l2, o);
    }
    __syncthreads();
    if (lane == 0) { red1[wid] = l1; red2[wid] = l2; }
    __syncthreads();
    l1 = red1[0] + red1[1] + red1[2] + red1[3];
    l2 = red2[0] + red2[1] + red2[2] + red2[3];

    const float mp = __ldg(mixp);
    const float rr = (tanhf(mp) + 1.f) * 0.5f;
    const float c1 = (1.f - rr) / l1;
    const float c2 = rr / l2;
#pragma unroll
    for (int t = 0; t < 4; t++) {
        int j = tid + t * 128;
        Srow[j] = c1 * __expf(sv[t] - m1) + c2 * __expf(bv[t] - m2);
    }
}

// ---------------------------------------------------------------------------
// Batched PV (unchanged)
// ---------------------------------------------------------------------------
__global__ __launch_bounds__(256) void pv_kernel()
{
    const int bh = blockIdx.y;
    const int b = bh >> 4;
    const int h = bh & 15;
    const int i0 = blockIdx.x * 64;

    __shared__ float Ps[64][68];
    __shared__ float Vs[64][68];

    const int tid = threadIdx.x;
    const int tRow = tid >> 4;
    const int tCol = tid & 15;

    float acc[4][4];
#pragma unroll
    for (int a = 0; a < 4; a++)
#pragma unroll
        for (int c = 0; c < 4; c++) acc[a][c] = 0.f;

    for (int j0 = 0; j0 < L_; j0 += 64) {
#pragma unroll
        for (int t = 0; t < 4; t++) {
            int f  = tid + t * 256;
            int r  = f >> 4;
            int c4 = (f & 15) * 4;
            *reinterpret_cast<float4*>(&Ps[r][c4]) =
                *reinterpret_cast<const float4*>(&g_S[((size_t)bh * L_ + i0 + r) * L_ + j0 + c4]);
            *reinterpret_cast<float4*>(&Vs[r][c4]) =
                *reinterpret_cast<const float4*>(&g_V[(size_t)(b * L_ + j0 + r) * DIM_ + h * HD_ + c4]);
        }
        __syncthreads();
#pragma unroll 4
        for (int j = 0; j < 64; j++) {
            float pv[4], vv[4];
#pragma unroll
            for (int t = 0; t < 4; t++) {
                pv[t] = Ps[tRow + 16 * t][j];
                vv[t] = Vs[j][tCol + 16 * t];
            }
#pragma unroll
            for (int a = 0; a < 4; a++)
#pragma unroll
                for (int c = 0; c < 4; c++)
                    acc[a][c] = fmaf(pv[a], vv[c], acc[a][c]);
        }
        __syncthreads();
    }

#pragma unroll
    for (int a = 0; a < 4; a++) {
        int i = i0 + tRow + 16 * a;
#pragma unroll
        for (int c = 0; c < 4; c++) {
            int d = tCol + 16 * c;
            g_AO[(size_t)(b * L_ + i) * DIM_ + h * HD_ + d] = acc[a][c];
        }
    }
}

// ---------------------------------------------------------------------------
extern "C" void kernel_launch(void* const* d_in, const int* in_sizes, int n_in,
                              void* d_out, int out_size)
{
    const float* seq1 = (const float*)d_in[0];
    const float* seq2 = (const float*)d_in[1];
    const float* atc1 = (const float*)d_in[2];
    const float* atc2 = (const float*)d_in[3];
    const float* Wq   = (const float*)d_in[4];
    const float* bq   = (const float*)d_in[5];
    const float* Wk   = (const float*)d_in[6];
    const float* bk   = (const float*)d_in[7];
    const float* Wv   = (const float*)d_in[8];
    const float* bv   = (const float*)d_in[9];
    const float* Wo   = (const float*)d_in[10];
    const float* bo   = (const float*)d_in[11];
    const float* U    = (const float*)d_in[12];
    const float* mixp = (const float*)d_in[13];
    float* out = (float*)d_out;

    const int M = B_ * L_;                 // 4096
    dim3 gproj(DIM_ / 128, M / 128);       // (8, 32)

    // Projections (tf32 mma.sync) -> g_Q / g_K / g_V
    gemm_tf32_mma<<<gproj, 256>>>(seq1, 0, Wq, bq, nullptr, 0);
    gemm_tf32_mma<<<gproj, 256>>>(seq2, 0, Wk, bk, nullptr, 1);
    gemm_tf32_mma<<<gproj, 256>>>(seq2, 0, Wv, bv, nullptr, 2);

    // Scores
    qk_kernel<<<dim3(L_ / 64, L_ / 64, B_ * H_), 256>>>();

    // Dual softmax + bio bias + mix (in place)
    softmax_mix_kernel<<<B_ * H_ * L_, 128>>>(atc1, atc2, U, mixp);

    // attn @ V  -> g_AO
    pv_kernel<<<dim3(L_ / 64, B_ * H_), 256>>>();

    // Output projection (tf32 mma.sync) -> d_out
    gemm_tf32_mma<<<gproj, 256>>>(nullptr, 1, Wo, bo, out, 3);
}

// round 4
// speedup vs baseline: 2.4557x; 1.2771x over previous
#include <cuda_runtime.h>
#include <math.h>
#include <cstdint>

#define B_   8
#define H_   16
#define L_   512
#define DIM_ 1024
#define HD_  64

// Scratch (device globals: allocation-free per harness rules)
__device__ float g_Q [B_ * L_ * DIM_];
__device__ float g_K [B_ * L_ * DIM_];
__device__ float g_V [B_ * L_ * DIM_];
__device__ float g_AO[B_ * L_ * DIM_];
__device__ float g_S [B_ * H_ * L_ * L_];     // 134 MB scores -> mixed attn

// ===========================================================================
// tf32 helpers (baseline PTX, supported on compute_103)
// ===========================================================================
__device__ __forceinline__ uint32_t f2tf32(float f) {
    uint32_t o;
    asm("cvt.rna.tf32.f32 %0, %1;" : "=r"(o) : "f"(f));
    return o;
}

__device__ __forceinline__ void mma_tf32(
    float& d0, float& d1, float& d2, float& d3,
    uint32_t a0, uint32_t a1, uint32_t a2, uint32_t a3,
    uint32_t b0, uint32_t b1)
{
    asm volatile(
        "mma.sync.aligned.m16n8k8.row.col.f32.tf32.tf32.f32 "
        "{%0,%1,%2,%3}, {%4,%5,%6,%7}, {%8,%9}, {%0,%1,%2,%3};"
        : "+f"(d0), "+f"(d1), "+f"(d2), "+f"(d3)
        : "r"(a0), "r"(a1), "r"(a2), "r"(a3), "r"(b0), "r"(b1));
}

// ===========================================================================
// tf32 mma.sync GEMM:  C[M,1024] = A[M,1024] @ W[1024,1024]^T + bias
// CTA tile 128x128, 8 warps (4m x 2n), warp tile 32x64.
// K-chunk 16, double-buffered SMEM, stride-20 padding (conflict-free frags).
// mode 0: fused QKV (z=0 Q, z=1 K, z=2 V), mode 1: output proj -> C_ext
// ===========================================================================
#define GK    1024
#define KB    16
#define NCH   (GK / KB)      // 64
#define SST   20             // smem row stride in words

__global__ __launch_bounds__(256, 2) void gemm_tf32_mma(
    const float* __restrict__ seq1, const float* __restrict__ seq2,
    const float* __restrict__ Wq, const float* __restrict__ bq,
    const float* __restrict__ Wk, const float* __restrict__ bk,
    const float* __restrict__ Wv, const float* __restrict__ bv,
    float* __restrict__ C_ext, int mode)
{
    const float* A;
    const float* W;
    const float* bias;
    float* C;
    if (mode == 1) {
        A = (const float*)g_AO; W = Wq; bias = bq; C = C_ext;
    } else {
        const int z = blockIdx.z;
        if (z == 0)      { A = seq1; W = Wq; bias = bq; C = g_Q; }
        else if (z == 1) { A = seq2; W = Wk; bias = bk; C = g_K; }
        else             { A = seq2; W = Wv; bias = bv; C = g_V; }
    }

    __shared__ uint32_t As[2][128 * SST];
    __shared__ uint32_t Bs[2][128 * SST];
    __shared__ float s_bias[128];

    const int tid  = threadIdx.x;
    const int wid  = tid >> 5;
    const int lane = tid & 31;
    const int g    = lane >> 2;
    const int tg   = lane & 3;
    const int mrow = (wid >> 1) * 32;
    const int ncol = (wid & 1) * 64;

    const float* Arow = A + (size_t)blockIdx.y * 128 * GK;
    const float* Wrow = W + (size_t)blockIdx.x * 128 * GK;

    if (tid < 128) s_bias[tid] = bias[blockIdx.x * 128 + tid];

    const int s0 = tid, s1 = tid + 256;
    const int r0 = s0 >> 2, k40 = (s0 & 3) << 2;
    const int r1 = s1 >> 2, k41 = (s1 & 3) << 2;

    float acc[2][8][4];
#pragma unroll
    for (int mt = 0; mt < 2; mt++)
#pragma unroll
        for (int nt = 0; nt < 8; nt++)
#pragma unroll
            for (int e = 0; e < 4; e++) acc[mt][nt][e] = 0.f;

    {
        float4 va0 = __ldg((const float4*)(Arow + (size_t)r0 * GK + k40));
        float4 va1 = __ldg((const float4*)(Arow + (size_t)r1 * GK + k41));
        float4 vb0 = __ldg((const float4*)(Wrow + (size_t)r0 * GK + k40));
        float4 vb1 = __ldg((const float4*)(Wrow + (size_t)r1 * GK + k41));
        uint4 u;
        u.x = f2tf32(va0.x); u.y = f2tf32(va0.y); u.z = f2tf32(va0.z); u.w = f2tf32(va0.w);
        *(uint4*)&As[0][r0 * SST + k40] = u;
        u.x = f2tf32(va1.x); u.y = f2tf32(va1.y); u.z = f2tf32(va1.z); u.w = f2tf32(va1.w);
        *(uint4*)&As[0][r1 * SST + k41] = u;
        u.x = f2tf32(vb0.x); u.y = f2tf32(vb0.y); u.z = f2tf32(vb0.z); u.w = f2tf32(vb0.w);
        *(uint4*)&Bs[0][r0 * SST + k40] = u;
        u.x = f2tf32(vb1.x); u.y = f2tf32(vb1.y); u.z = f2tf32(vb1.z); u.w = f2tf32(vb1.w);
        *(uint4*)&Bs[0][r1 * SST + k41] = u;
    }
    __syncthreads();

    for (int i = 0; i < NCH; i++) {
        const int st = i & 1;
        float4 va0, va1, vb0, vb1;
        const bool more = (i + 1 < NCH);
        if (more) {
            const int ko = (i + 1) * KB;
            va0 = __ldg((const float4*)(Arow + (size_t)r0 * GK + ko + k40));
            va1 = __ldg((const float4*)(Arow + (size_t)r1 * GK + ko + k41));
            vb0 = __ldg((const float4*)(Wrow + (size_t)r0 * GK + ko + k40));
            vb1 = __ldg((const float4*)(Wrow + (size_t)r1 * GK + ko + k41));
        }

#pragma unroll
        for (int ks = 0; ks < 2; ks++) {
            uint32_t a[2][4];
#pragma unroll
            for (int mt = 0; mt < 2; mt++) {
                const int rb = mrow + mt * 16 + g;
                a[mt][0] = As[st][(rb)     * SST + ks * 8 + tg];
                a[mt][1] = As[st][(rb + 8) * SST + ks * 8 + tg];
                a[mt][2] = As[st][(rb)     * SST + ks * 8 + tg + 4];
                a[mt][3] = As[st][(rb + 8) * SST + ks * 8 + tg + 4];
            }
#pragma unroll
            for (int nt = 0; nt < 8; nt++) {
                const int rw = ncol + nt * 8 + g;
                uint32_t b0 = Bs[st][rw * SST + ks * 8 + tg];
                uint32_t b1 = Bs[st][rw * SST + ks * 8 + tg + 4];
#pragma unroll
                for (int mt = 0; mt < 2; mt++)
                    mma_tf32(acc[mt][nt][0], acc[mt][nt][1], acc[mt][nt][2], acc[mt][nt][3],
                             a[mt][0], a[mt][1], a[mt][2], a[mt][3], b0, b1);
            }
        }

        if (more) {
            const int ns = st ^ 1;
            uint4 u;
            u.x = f2tf32(va0.x); u.y = f2tf32(va0.y); u.z = f2tf32(va0.z); u.w = f2tf32(va0.w);
            *(uint4*)&As[ns][r0 * SST + k40] = u;
            u.x = f2tf32(va1.x); u.y = f2tf32(va1.y); u.z = f2tf32(va1.z); u.w = f2tf32(va1.w);
            *(uint4*)&As[ns][r1 * SST + k41] = u;
            u.x = f2tf32(vb0.x); u.y = f2tf32(vb0.y); u.z = f2tf32(vb0.z); u.w = f2tf32(vb0.w);
            *(uint4*)&Bs[ns][r0 * SST + k40] = u;
            u.x = f2tf32(vb1.x); u.y = f2tf32(vb1.y); u.z = f2tf32(vb1.z); u.w = f2tf32(vb1.w);
            *(uint4*)&Bs[ns][r1 * SST + k41] = u;
            __syncthreads();
        }
    }

#pragma unroll
    for (int mt = 0; mt < 2; mt++) {
#pragma unroll
        for (int nt = 0; nt < 8; nt++) {
            const int row = mrow + mt * 16 + g;
            const int col = ncol + nt * 8 + 2 * tg;
            const int gm0 = blockIdx.y * 128 + row;
            const int gc  = blockIdx.x * 128 + col;
            float2 o;
            o.x = acc[mt][nt][0] + s_bias[col];
            o.y = acc[mt][nt][1] + s_bias[col + 1];
            *(float2*)(C + (size_t)gm0 * DIM_ + gc) = o;
            o.x = acc[mt][nt][2] + s_bias[col];
            o.y = acc[mt][nt][3] + s_bias[col + 1];
            *(float2*)(C + (size_t)(gm0 + 8) * DIM_ + gc) = o;
        }
    }
}

// ===========================================================================
// QK^T via tf32 mma: S[bh, i, j] = (1/8) sum_d Q_i,d K_j,d
// CTA tile 128(i) x 128(j), K=64 in two 32-chunks (single-buffered).
// 8 warps 4m x 2n, warp tile 32x64.
// ===========================================================================
#define QST 36   // 32-word rows padded to 36 (conflict-free: 4g+tg covers 0..31)

__global__ __launch_bounds__(256, 2) void qk_mma_kernel()
{
    const int bh = blockIdx.z;
    const int b = bh >> 4;
    const int h = bh & 15;
    const int i0 = blockIdx.y * 128;
    const int j0 = blockIdx.x * 128;

    __shared__ uint32_t Qs[128 * QST];
    __shared__ uint32_t Ks[128 * QST];

    const int tid  = threadIdx.x;
    const int wid  = tid >> 5;
    const int lane = tid & 31;
    const int g    = lane >> 2;
    const int tg   = lane & 3;
    const int mrow = (wid >> 1) * 32;
    const int ncol = (wid & 1) * 64;

    float acc[2][8][4];
#pragma unroll
    for (int mt = 0; mt < 2; mt++)
#pragma unroll
        for (int nt = 0; nt < 8; nt++)
#pragma unroll
            for (int e = 0; e < 4; e++) acc[mt][nt][e] = 0.f;

    // load slots: 128 rows x 8 float4 per tile -> 1024 slots, 4 per thread
    for (int ch = 0; ch < 2; ch++) {
        if (ch) __syncthreads();
#pragma unroll
        for (int t = 0; t < 4; t++) {
            const int s  = tid + t * 256;
            const int r  = s >> 3;
            const int c4 = (s & 7) << 2;
            float4 q = *(const float4*)&g_Q[(size_t)(b * L_ + i0 + r) * DIM_ + h * HD_ + ch * 32 + c4];
            float4 k = *(const float4*)&g_K[(size_t)(b * L_ + j0 + r) * DIM_ + h * HD_ + ch * 32 + c4];
            uint4 u;
            u.x = f2tf32(q.x); u.y = f2tf32(q.y); u.z = f2tf32(q.z); u.w = f2tf32(q.w);
            *(uint4*)&Qs[r * QST + c4] = u;
            u.x = f2tf32(k.x); u.y = f2tf32(k.y); u.z = f2tf32(k.z); u.w = f2tf32(k.w);
            *(uint4*)&Ks[r * QST + c4] = u;
        }
        __syncthreads();

#pragma unroll
        for (int ks = 0; ks < 4; ks++) {
            uint32_t a[2][4];
#pragma unroll
            for (int mt = 0; mt < 2; mt++) {
                const int rb = mrow + mt * 16 + g;
                a[mt][0] = Qs[(rb)     * QST + ks * 8 + tg];
                a[mt][1] = Qs[(rb + 8) * QST + ks * 8 + tg];
                a[mt][2] = Qs[(rb)     * QST + ks * 8 + tg + 4];
                a[mt][3] = Qs[(rb + 8) * QST + ks * 8 + tg + 4];
            }
#pragma unroll
            for (int nt = 0; nt < 8; nt++) {
                const int rw = ncol + nt * 8 + g;
                uint32_t b0 = Ks[rw * QST + ks * 8 + tg];
                uint32_t b1 = Ks[rw * QST + ks * 8 + tg + 4];
#pragma unroll
                for (int mt = 0; mt < 2; mt++)
                    mma_tf32(acc[mt][nt][0], acc[mt][nt][1], acc[mt][nt][2], acc[mt][nt][3],
                             a[mt][0], a[mt][1], a[mt][2], a[mt][3], b0, b1);
            }
        }
    }

#pragma unroll
    for (int mt = 0; mt < 2; mt++) {
#pragma unroll
        for (int nt = 0; nt < 8; nt++) {
            const int i = i0 + mrow + mt * 16 + g;
            const int j = j0 + ncol + nt * 8 + 2 * tg;
            float* Sr0 = g_S + ((size_t)bh * L_ + i) * L_ + j;
            float2 o;
            o.x = acc[mt][nt][0] * 0.125f;
            o.y = acc[mt][nt][1] * 0.125f;
            *(float2*)Sr0 = o;
            o.x = acc[mt][nt][2] * 0.125f;
            o.y = acc[mt][nt][3] * 0.125f;
            *(float2*)(Sr0 + 8 * (int)L_) = o;
        }
    }
}

// ===========================================================================
// PV via tf32 mma: AO[b,i, h*64+d] = sum_j attn[bh,i,j] V[bh,j,d]
// CTA tile 128(i) x 64(d), K=512 in 32-chunks (single-buffered).
// 8 warps 4m x 2n, warp tile 32x32.
// ===========================================================================
#define VST 72   // 64-word rows padded to 72 (8tg+g covers 0..31: conflict-free)

__global__ __launch_bounds__(256, 2) void pv_mma_kernel()
{
    const int bh = blockIdx.y;
    const int b = bh >> 4;
    const int h = bh & 15;
    const int i0 = blockIdx.x * 128;

    __shared__ uint32_t As[128 * QST];   // attn tile 128 x 32
    __shared__ uint32_t Vs[32 * VST];    // V tile 32 x 64

    const int tid  = threadIdx.x;
    const int wid  = tid >> 5;
    const int lane = tid & 31;
    const int g    = lane >> 2;
    const int tg   = lane & 3;
    const int mrow = (wid >> 1) * 32;
    const int ncol = (wid & 1) * 32;

    float acc[2][4][4];
#pragma unroll
    for (int mt = 0; mt < 2; mt++)
#pragma unroll
        for (int nt = 0; nt < 4; nt++)
#pragma unroll
            for (int e = 0; e < 4; e++) acc[mt][nt][e] = 0.f;

    for (int ch = 0; ch < 16; ch++) {
        if (ch) __syncthreads();
        const int j0 = ch * 32;
        // attn tile: 1024 float4 slots, 4/thread
#pragma unroll
        for (int t = 0; t < 4; t++) {
            const int s  = tid + t * 256;
            const int r  = s >> 3;
            const int c4 = (s & 7) << 2;
            float4 p = *(const float4*)&g_S[((size_t)bh * L_ + i0 + r) * L_ + j0 + c4];
            uint4 u;
            u.x = f2tf32(p.x); u.y = f2tf32(p.y); u.z = f2tf32(p.z); u.w = f2tf32(p.w);
            *(uint4*)&As[r * QST + c4] = u;
        }
        // V tile: 32x64 = 512 float4 slots, 2/thread
#pragma unroll
        for (int t = 0; t < 2; t++) {
            const int s  = tid + t * 256;
            const int r  = s >> 4;
            const int c4 = (s & 15) << 2;
            float4 v = *(const float4*)&g_V[(size_t)(b * L_ + j0 + r) * DIM_ + h * HD_ + c4];
            uint4 u;
            u.x = f2tf32(v.x); u.y = f2tf32(v.y); u.z = f2tf32(v.z); u.w = f2tf32(v.w);
            *(uint4*)&Vs[r * VST + c4] = u;
        }
        __syncthreads();

#pragma unroll
        for (int ks = 0; ks < 4; ks++) {
            uint32_t a[2][4];
#pragma unroll
            for (int mt = 0; mt < 2; mt++) {
                const int rb = mrow + mt * 16 + g;
                a[mt][0] = As[(rb)     * QST + ks * 8 + tg];
                a[mt][1] = As[(rb + 8) * QST + ks * 8 + tg];
                a[mt][2] = As[(rb)     * QST + ks * 8 + tg + 4];
                a[mt][3] = As[(rb + 8) * QST + ks * 8 + tg + 4];
            }
#pragma unroll
            for (int nt = 0; nt < 4; nt++) {
                const int n = ncol + nt * 8 + g;
                uint32_t b0 = Vs[(ks * 8 + tg)     * VST + n];
                uint32_t b1 = Vs[(ks * 8 + tg + 4) * VST + n];
#pragma unroll
                for (int mt = 0; mt < 2; mt++)
                    mma_tf32(acc[mt][nt][0], acc[mt][nt][1], acc[mt][nt][2], acc[mt][nt][3],
                             a[mt][0], a[mt][1], a[mt][2], a[mt][3], b0, b1);
            }
        }
    }

#pragma unroll
    for (int mt = 0; mt < 2; mt++) {
#pragma unroll
        for (int nt = 0; nt < 4; nt++) {
            const int i = i0 + mrow + mt * 16 + g;
            const int d = ncol + nt * 8 + 2 * tg;
            float* Ao = g_AO + (size_t)(b * L_ + i) * DIM_ + h * HD_ + d;
            float2 o;
            o.x = acc[mt][nt][0];
            o.y = acc[mt][nt][1];
            *(float2*)Ao = o;
            o.x = acc[mt][nt][2];
            o.y = acc[mt][nt][3];
            *(float2*)(Ao + 8 * (size_t)DIM_) = o;
        }
    }
}

// ---------------------------------------------------------------------------
// Dual softmax + Atchley bias + mix (unchanged, known-passing)
// ---------------------------------------------------------------------------
__global__ __launch_bounds__(128) void softmax_mix_kernel(
    const float* __restrict__ atc1, const float* __restrict__ atc2,
    const float* __restrict__ U, const float* __restrict__ mixp)
{
    const int row = blockIdx.x;
    const int bh = row >> 9;
    const int i  = row & 511;
    const int b  = bh >> 4;
    const int h  = bh & 15;
    const int tid = threadIdx.x;

    float a1u[5];
    {
        float a1[5];
#pragma unroll
        for (int p = 0; p < 5; p++) a1[p] = __ldg(&atc1[(size_t)(b * L_ + i) * 5 + p]);
#pragma unroll
        for (int q = 0; q < 5; q++) {
            float s = 0.f;
#pragma unroll
            for (int p = 0; p < 5; p++) s = fmaf(a1[p], __ldg(&U[h * 25 + p * 5 + q]), s);
            a1u[q] = s;
        }
    }

    float* Srow = g_S + (size_t)row * L_;
    float sv[4], bv[4];
#pragma unroll
    for (int t = 0; t < 4; t++) {
        int j = tid + t * 128;
        sv[t] = Srow[j];
        const float* a2 = atc2 + (size_t)(b * L_ + j) * 5;
        float s = 0.f;
#pragma unroll
        for (int q = 0; q < 5; q++) s = fmaf(a1u[q], __ldg(&a2[q]), s);
        bv[t] = s;
    }

    __shared__ float red1[4], red2[4];
    const int wid = tid >> 5, lane = tid & 31;

    float m1 = fmaxf(fmaxf(sv[0], sv[1]), fmaxf(sv[2], sv[3]));
    float m2 = fmaxf(fmaxf(bv[0], bv[1]), fmaxf(bv[2], bv[3]));
#pragma unroll
    for (int o = 16; o; o >>= 1) {
        m1 = fmaxf(m1, __shfl_xor_sync(0xffffffffu, m1, o));
        m2 = fmaxf(m2, __shfl_xor_sync(0xffffffffu, m2, o));
    }
    if (lane == 0) { red1[wid] = m1; red2[wid] = m2; }
    __syncthreads();
    m1 = fmaxf(fmaxf(red1[0], red1[1]), fmaxf(red1[2], red1[3]));
    m2 = fmaxf(fmaxf(red2[0], red2[1]), fmaxf(red2[2], red2[3]));

    float l1 = 0.f, l2 = 0.f;
#pragma unroll
    for (int t = 0; t < 4; t++) {
        l1 += __expf(sv[t] - m1);
        l2 += __expf(bv[t] - m2);
    }
#pragma unroll
    for (int o = 16; o; o >>= 1) {
        l1 += __shfl_xor_sync(0xffffffffu, l1, o);
        l2 += __shfl_xor_sync(0xffffffffu, l2, o);
    }
    __syncthreads();
    if (lane == 0) { red1[wid] = l1; red2[wid] = l2; }
    __syncthreads();
    l1 = red1[0] + red1[1] + red1[2] + red1[3];
    l2 = red2[0] + red2[1] + red2[2] + red2[3];

    const float mp = __ldg(mixp);
    const float rr = (tanhf(mp) + 1.f) * 0.5f;
    const float c1 = (1.f - rr) / l1;
    const float c2 = rr / l2;
#pragma unroll
    for (int t = 0; t < 4; t++) {
        int j = tid + t * 128;
        Srow[j] = c1 * __expf(sv[t] - m1) + c2 * __expf(bv[t] - m2);
    }
}

// ---------------------------------------------------------------------------
extern "C" void kernel_launch(void* const* d_in, const int* in_sizes, int n_in,
                              void* d_out, int out_size)
{
    const float* seq1 = (const float*)d_in[0];
    const float* seq2 = (const float*)d_in[1];
    const float* atc1 = (const float*)d_in[2];
    const float* atc2 = (const float*)d_in[3];
    const float* Wq   = (const float*)d_in[4];
    const float* bq   = (const float*)d_in[5];
    const float* Wk   = (const float*)d_in[6];
    const float* bk   = (const float*)d_in[7];
    const float* Wv   = (const float*)d_in[8];
    const float* bv   = (const float*)d_in[9];
    const float* Wo   = (const float*)d_in[10];
    const float* bo   = (const float*)d_in[11];
    const float* U    = (const float*)d_in[12];
    const float* mixp = (const float*)d_in[13];
    float* out = (float*)d_out;

    const int M = B_ * L_;                       // 4096

    // Fused Q/K/V projections (z selects)
    gemm_tf32_mma<<<dim3(DIM_ / 128, M / 128, 3), 256>>>(
        seq1, seq2, Wq, bq, Wk, bk, Wv, bv, nullptr, 0);

    // Scores (tf32 mma)
    qk_mma_kernel<<<dim3(L_ / 128, L_ / 128, B_ * H_), 256>>>();

    // Dual softmax + bio bias + mix (in place)
    softmax_mix_kernel<<<B_ * H_ * L_, 128>>>(atc1, atc2, U, mixp);

    // attn @ V (tf32 mma) -> g_AO
    pv_mma_kernel<<<dim3(L_ / 128, B_ * H_), 256>>>();

    // Output projection -> d_out
    gemm_tf32_mma<<<dim3(DIM_ / 128, M / 128, 1), 256>>>(
        nullptr, nullptr, Wo, bo, nullptr, nullptr, nullptr, nullptr, out, 1);
}

// round 5
// speedup vs baseline: 2.7822x; 1.1329x over previous
#include <cuda_runtime.h>
#include <math.h>
#include <cstdint>

#define B_   8
#define H_   16
#define L_   512
#define DIM_ 1024
#define HD_  64

// Scratch (device globals: allocation-free per harness rules)
__device__ float g_Q [B_ * L_ * DIM_];
__device__ float g_K [B_ * L_ * DIM_];
__device__ float g_V [B_ * L_ * DIM_];
__device__ float g_AO[B_ * L_ * DIM_];

// ===========================================================================
// tf32 helpers (baseline PTX, supported on compute_103)
// ===========================================================================
__device__ __forceinline__ uint32_t f2tf32(float f) {
    uint32_t o;
    asm("cvt.rna.tf32.f32 %0, %1;" : "=r"(o) : "f"(f));
    return o;
}

__device__ __forceinline__ void mma_tf32(
    float& d0, float& d1, float& d2, float& d3,
    uint32_t a0, uint32_t a1, uint32_t a2, uint32_t a3,
    uint32_t b0, uint32_t b1)
{
    asm volatile(
        "mma.sync.aligned.m16n8k8.row.col.f32.tf32.tf32.f32 "
        "{%0,%1,%2,%3}, {%4,%5,%6,%7}, {%8,%9}, {%0,%1,%2,%3};"
        : "+f"(d0), "+f"(d1), "+f"(d2), "+f"(d3)
        : "r"(a0), "r"(a1), "r"(a2), "r"(a3), "r"(b0), "r"(b1));
}

// ===========================================================================
// Projection GEMM (unchanged, known-passing):
// C[M,1024] = A[M,1024] @ W[1024,1024]^T + bias
// mode 0: fused QKV (z=0 Q, z=1 K, z=2 V), mode 1: output proj -> C_ext
// ===========================================================================
#define GK    1024
#define KB    16
#define NCH   (GK / KB)
#define SST   20

__global__ __launch_bounds__(256, 2) void gemm_tf32_mma(
    const float* __restrict__ seq1, const float* __restrict__ seq2,
    const float* __restrict__ Wq, const float* __restrict__ bq,
    const float* __restrict__ Wk, const float* __restrict__ bk,
    const float* __restrict__ Wv, const float* __restrict__ bv,
    float* __restrict__ C_ext, int mode)
{
    const float* A;
    const float* W;
    const float* bias;
    float* C;
    if (mode == 1) {
        A = (const float*)g_AO; W = Wq; bias = bq; C = C_ext;
    } else {
        const int z = blockIdx.z;
        if (z == 0)      { A = seq1; W = Wq; bias = bq; C = g_Q; }
        else if (z == 1) { A = seq2; W = Wk; bias = bk; C = g_K; }
        else             { A = seq2; W = Wv; bias = bv; C = g_V; }
    }

    __shared__ uint32_t As[2][128 * SST];
    __shared__ uint32_t Bs[2][128 * SST];
    __shared__ float s_bias[128];

    const int tid  = threadIdx.x;
    const int wid  = tid >> 5;
    const int lane = tid & 31;
    const int g    = lane >> 2;
    const int tg   = lane & 3;
    const int mrow = (wid >> 1) * 32;
    const int ncol = (wid & 1) * 64;

    const float* Arow = A + (size_t)blockIdx.y * 128 * GK;
    const float* Wrow = W + (size_t)blockIdx.x * 128 * GK;

    if (tid < 128) s_bias[tid] = bias[blockIdx.x * 128 + tid];

    const int s0 = tid, s1 = tid + 256;
    const int r0 = s0 >> 2, k40 = (s0 & 3) << 2;
    const int r1 = s1 >> 2, k41 = (s1 & 3) << 2;

    float acc[2][8][4];
#pragma unroll
    for (int mt = 0; mt < 2; mt++)
#pragma unroll
        for (int nt = 0; nt < 8; nt++)
#pragma unroll
            for (int e = 0; e < 4; e++) acc[mt][nt][e] = 0.f;

    {
        float4 va0 = __ldg((const float4*)(Arow + (size_t)r0 * GK + k40));
        float4 va1 = __ldg((const float4*)(Arow + (size_t)r1 * GK + k41));
        float4 vb0 = __ldg((const float4*)(Wrow + (size_t)r0 * GK + k40));
        float4 vb1 = __ldg((const float4*)(Wrow + (size_t)r1 * GK + k41));
        uint4 u;
        u.x = f2tf32(va0.x); u.y = f2tf32(va0.y); u.z = f2tf32(va0.z); u.w = f2tf32(va0.w);
        *(uint4*)&As[0][r0 * SST + k40] = u;
        u.x = f2tf32(va1.x); u.y = f2tf32(va1.y); u.z = f2tf32(va1.z); u.w = f2tf32(va1.w);
        *(uint4*)&As[0][r1 * SST + k41] = u;
        u.x = f2tf32(vb0.x); u.y = f2tf32(vb0.y); u.z = f2tf32(vb0.z); u.w = f2tf32(vb0.w);
        *(uint4*)&Bs[0][r0 * SST + k40] = u;
        u.x = f2tf32(vb1.x); u.y = f2tf32(vb1.y); u.z = f2tf32(vb1.z); u.w = f2tf32(vb1.w);
        *(uint4*)&Bs[0][r1 * SST + k41] = u;
    }
    __syncthreads();

    for (int i = 0; i < NCH; i++) {
        const int st = i & 1;
        float4 va0, va1, vb0, vb1;
        const bool more = (i + 1 < NCH);
        if (more) {
            const int ko = (i + 1) * KB;
            va0 = __ldg((const float4*)(Arow + (size_t)r0 * GK + ko + k40));
            va1 = __ldg((const float4*)(Arow + (size_t)r1 * GK + ko + k41));
            vb0 = __ldg((const float4*)(Wrow + (size_t)r0 * GK + ko + k40));
            vb1 = __ldg((const float4*)(Wrow + (size_t)r1 * GK + ko + k41));
        }

#pragma unroll
        for (int ks = 0; ks < 2; ks++) {
            uint32_t a[2][4];
#pragma unroll
            for (int mt = 0; mt < 2; mt++) {
                const int rb = mrow + mt * 16 + g;
                a[mt][0] = As[st][(rb)     * SST + ks * 8 + tg];
                a[mt][1] = As[st][(rb + 8) * SST + ks * 8 + tg];
                a[mt][2] = As[st][(rb)     * SST + ks * 8 + tg + 4];
                a[mt][3] = As[st][(rb + 8) * SST + ks * 8 + tg + 4];
            }
#pragma unroll
            for (int nt = 0; nt < 8; nt++) {
                const int rw = ncol + nt * 8 + g;
                uint32_t b0 = Bs[st][rw * SST + ks * 8 + tg];
                uint32_t b1 = Bs[st][rw * SST + ks * 8 + tg + 4];
#pragma unroll
                for (int mt = 0; mt < 2; mt++)
                    mma_tf32(acc[mt][nt][0], acc[mt][nt][1], acc[mt][nt][2], acc[mt][nt][3],
                             a[mt][0], a[mt][1], a[mt][2], a[mt][3], b0, b1);
            }
        }

        if (more) {
            const int ns = st ^ 1;
            uint4 u;
            u.x = f2tf32(va0.x); u.y = f2tf32(va0.y); u.z = f2tf32(va0.z); u.w = f2tf32(va0.w);
            *(uint4*)&As[ns][r0 * SST + k40] = u;
            u.x = f2tf32(va1.x); u.y = f2tf32(va1.y); u.z = f2tf32(va1.z); u.w = f2tf32(va1.w);
            *(uint4*)&As[ns][r1 * SST + k41] = u;
            u.x = f2tf32(vb0.x); u.y = f2tf32(vb0.y); u.z = f2tf32(vb0.z); u.w = f2tf32(vb0.w);
            *(uint4*)&Bs[ns][r0 * SST + k40] = u;
            u.x = f2tf32(vb1.x); u.y = f2tf32(vb1.y); u.z = f2tf32(vb1.z); u.w = f2tf32(vb1.w);
            *(uint4*)&Bs[ns][r1 * SST + k41] = u;
            __syncthreads();
        }
    }

#pragma unroll
    for (int mt = 0; mt < 2; mt++) {
#pragma unroll
        for (int nt = 0; nt < 8; nt++) {
            const int row = mrow + mt * 16 + g;
            const int col = ncol + nt * 8 + 2 * tg;
            const int gm0 = blockIdx.y * 128 + row;
            const int gc  = blockIdx.x * 128 + col;
            float2 o;
            o.x = acc[mt][nt][0] + s_bias[col];
            o.y = acc[mt][nt][1] + s_bias[col + 1];
            *(float2*)(C + (size_t)gm0 * DIM_ + gc) = o;
            o.x = acc[mt][nt][2] + s_bias[col];
            o.y = acc[mt][nt][3] + s_bias[col + 1];
            *(float2*)(C + (size_t)(gm0 + 8) * DIM_ + gc) = o;
        }
    }
}

// ===========================================================================
// Fused attention: QK^T -> dual online softmax (+Atchley bias) -> mix -> @V
// CTA: one (b,h) x 128-row i-tile. 8 warps, each owns 16 rows.
// j-chunks of 64; K then V share one SMEM buffer.
// No g_S. Output -> g_AO (b, i, h*64+d).
// ===========================================================================
#define KST 68   // K smem stride (words): banks 4g+tg conflict-free
#define VST 72   // V smem stride (words): banks 8tg+g conflict-free

__global__ __launch_bounds__(256) void attn_fused_kernel(
    const float* __restrict__ atc1, const float* __restrict__ atc2,
    const float* __restrict__ U, const float* __restrict__ mixp)
{
    const int bh = blockIdx.y;
    const int b  = bh >> 4;
    const int h  = bh & 15;
    const int i0 = blockIdx.x * 128;

    __shared__ uint32_t KVs[64 * VST];      // K (stride 68) then V (stride 72)
    __shared__ float Atc2s[64][5];

    const int tid  = threadIdx.x;
    const int wid  = tid >> 5;
    const int lane = tid & 31;
    const int g    = lane >> 2;
    const int tg   = lane & 3;
    const int wrow = wid * 16;              // warp's 16 rows within i-tile

    // --- Q fragments (one-time register gather), rows {g, g+8} of warp tile
    uint32_t qf[8][4];
    {
        const float* Qb = g_Q + (size_t)(b * L_ + i0 + wrow) * DIM_ + h * HD_;
#pragma unroll
        for (int kb = 0; kb < 8; kb++) {
            qf[kb][0] = f2tf32(__ldg(Qb + (size_t)g       * DIM_ + kb * 8 + tg));
            qf[kb][1] = f2tf32(__ldg(Qb + (size_t)(g + 8) * DIM_ + kb * 8 + tg));
            qf[kb][2] = f2tf32(__ldg(Qb + (size_t)g       * DIM_ + kb * 8 + tg + 4));
            qf[kb][3] = f2tf32(__ldg(Qb + (size_t)(g + 8) * DIM_ + kb * 8 + tg + 4));
        }
    }

    // --- a1u[q] = sum_p atc1[b,i,p] * U[h,p,q] for this thread's two rows
    float a1u0[5], a1u8[5];
    {
        const float* a1p = atc1 + (size_t)(b * L_ + i0 + wrow + g) * 5;
        float a1_0[5], a1_8[5];
#pragma unroll
        for (int p = 0; p < 5; p++) {
            a1_0[p] = __ldg(a1p + p);
            a1_8[p] = __ldg(a1p + 40 + p);   // +8 rows * 5
        }
#pragma unroll
        for (int q = 0; q < 5; q++) {
            float s0 = 0.f, s8 = 0.f;
#pragma unroll
            for (int p = 0; p < 5; p++) {
                float u = __ldg(&U[h * 25 + p * 5 + q]);
                s0 = fmaf(a1_0[p], u, s0);
                s8 = fmaf(a1_8[p], u, s8);
            }
            a1u0[q] = s0;
            a1u8[q] = s8;
        }
    }

    // online state: [0] row g, [1] row g+8
    float m1[2] = {-1e30f, -1e30f}, l1[2] = {0.f, 0.f};
    float m2[2] = {-1e30f, -1e30f}, l2[2] = {0.f, 0.f};
    float O1[8][4], O2[8][4];
#pragma unroll
    for (int nb = 0; nb < 8; nb++)
#pragma unroll
        for (int e = 0; e < 4; e++) { O1[nb][e] = 0.f; O2[nb][e] = 0.f; }

    for (int ch = 0; ch < 8; ch++) {
        const int j0 = ch * 64;
        __syncthreads();   // prior PV reads of KVs complete

        // load K chunk (64 x 64) -> KVs stride KST; stage atc2 chunk
#pragma unroll
        for (int t = 0; t < 4; t++) {
            const int s  = tid + t * 256;
            const int r  = s >> 4;
            const int c4 = (s & 15) << 2;
            float4 k = *(const float4*)&g_K[(size_t)(b * L_ + j0 + r) * DIM_ + h * HD_ + c4];
            uint4 u;
            u.x = f2tf32(k.x); u.y = f2tf32(k.y); u.z = f2tf32(k.z); u.w = f2tf32(k.w);
            *(uint4*)&KVs[r * KST + c4] = u;
        }
        if (tid < 64) {
#pragma unroll
            for (int q = 0; q < 5; q++)
                Atc2s[tid][q] = __ldg(&atc2[(size_t)(b * L_ + j0 + tid) * 5 + q]);
        }
        __syncthreads();

        // ---- QK mma: s1[nt][4] over 8 j-blocks
        float s1[8][4];
#pragma unroll
        for (int nt = 0; nt < 8; nt++)
#pragma unroll
            for (int e = 0; e < 4; e++) s1[nt][e] = 0.f;
#pragma unroll
        for (int kb = 0; kb < 8; kb++) {
#pragma unroll
            for (int nt = 0; nt < 8; nt++) {
                uint32_t b0 = KVs[(nt * 8 + g) * KST + kb * 8 + tg];
                uint32_t b1 = KVs[(nt * 8 + g) * KST + kb * 8 + tg + 4];
                mma_tf32(s1[nt][0], s1[nt][1], s1[nt][2], s1[nt][3],
                         qf[kb][0], qf[kb][1], qf[kb][2], qf[kb][3], b0, b1);
            }
        }
        // ---- bio scores in fragment layout
        float s2[8][4];
#pragma unroll
        for (int nt = 0; nt < 8; nt++) {
            const int c0 = nt * 8 + 2 * tg;
            float d00 = 0.f, d01 = 0.f, d80 = 0.f, d81 = 0.f;
#pragma unroll
            for (int q = 0; q < 5; q++) {
                float a20 = Atc2s[c0][q];
                float a21 = Atc2s[c0 + 1][q];
                d00 = fmaf(a1u0[q], a20, d00);
                d01 = fmaf(a1u0[q], a21, d01);
                d80 = fmaf(a1u8[q], a20, d80);
                d81 = fmaf(a1u8[q], a21, d81);
            }
            s2[nt][0] = d00; s2[nt][1] = d01; s2[nt][2] = d80; s2[nt][3] = d81;
#pragma unroll
            for (int e = 0; e < 4; e++) s1[nt][e] *= 0.125f;   // 1/sqrt(64)
        }

        // ---- chunk row maxes (quad shuffle; 4 lanes per row group)
        float cm1g = -1e30f, cm1h = -1e30f, cm2g = -1e30f, cm2h = -1e30f;
#pragma unroll
        for (int nt = 0; nt < 8; nt++) {
            cm1g = fmaxf(cm1g, fmaxf(s1[nt][0], s1[nt][1]));
            cm1h = fmaxf(cm1h, fmaxf(s1[nt][2], s1[nt][3]));
            cm2g = fmaxf(cm2g, fmaxf(s2[nt][0], s2[nt][1]));
            cm2h = fmaxf(cm2h, fmaxf(s2[nt][2], s2[nt][3]));
        }
#pragma unroll
        for (int o = 1; o <= 2; o <<= 1) {
            cm1g = fmaxf(cm1g, __shfl_xor_sync(0xffffffffu, cm1g, o));
            cm1h = fmaxf(cm1h, __shfl_xor_sync(0xffffffffu, cm1h, o));
            cm2g = fmaxf(cm2g, __shfl_xor_sync(0xffffffffu, cm2g, o));
            cm2h = fmaxf(cm2h, __shfl_xor_sync(0xffffffffu, cm2h, o));
        }

        // ---- online rescale
        float nm, al;
        nm = fmaxf(m1[0], cm1g); al = __expf(m1[0] - nm); m1[0] = nm; l1[0] *= al;
#pragma unroll
        for (int nb = 0; nb < 8; nb++) { O1[nb][0] *= al; O1[nb][1] *= al; }
        nm = fmaxf(m1[1], cm1h); al = __expf(m1[1] - nm); m1[1] = nm; l1[1] *= al;
#pragma unroll
        for (int nb = 0; nb < 8; nb++) { O1[nb][2] *= al; O1[nb][3] *= al; }
        nm = fmaxf(m2[0], cm2g); al = __expf(m2[0] - nm); m2[0] = nm; l2[0] *= al;
#pragma unroll
        for (int nb = 0; nb < 8; nb++) { O2[nb][0] *= al; O2[nb][1] *= al; }
        nm = fmaxf(m2[1], cm2h); al = __expf(m2[1] - nm); m2[1] = nm; l2[1] *= al;
#pragma unroll
        for (int nb = 0; nb < 8; nb++) { O2[nb][2] *= al; O2[nb][3] *= al; }

        // ---- exp in place + row sums
        float rs1g = 0.f, rs1h = 0.f, rs2g = 0.f, rs2h = 0.f;
#pragma unroll
        for (int nt = 0; nt < 8; nt++) {
            s1[nt][0] = __expf(s1[nt][0] - m1[0]); rs1g += s1[nt][0];
            s1[nt][1] = __expf(s1[nt][1] - m1[0]); rs1g += s1[nt][1];
            s1[nt][2] = __expf(s1[nt][2] - m1[1]); rs1h += s1[nt][2];
            s1[nt][3] = __expf(s1[nt][3] - m1[1]); rs1h += s1[nt][3];
            s2[nt][0] = __expf(s2[nt][0] - m2[0]); rs2g += s2[nt][0];
            s2[nt][1] = __expf(s2[nt][1] - m2[0]); rs2g += s2[nt][1];
            s2[nt][2] = __expf(s2[nt][2] - m2[1]); rs2h += s2[nt][2];
            s2[nt][3] = __expf(s2[nt][3] - m2[1]); rs2h += s2[nt][3];
        }
#pragma unroll
        for (int o = 1; o <= 2; o <<= 1) {
            rs1g += __shfl_xor_sync(0xffffffffu, rs1g, o);
            rs1h += __shfl_xor_sync(0xffffffffu, rs1h, o);
            rs2g += __shfl_xor_sync(0xffffffffu, rs2g, o);
            rs2h += __shfl_xor_sync(0xffffffffu, rs2h, o);
        }
        l1[0] += rs1g; l1[1] += rs1h;
        l2[0] += rs2g; l2[1] += rs2h;

        __syncthreads();   // all K reads done

        // load V chunk (64 x 64) -> KVs stride VST
#pragma unroll
        for (int t = 0; t < 4; t++) {
            const int s  = tid + t * 256;
            const int r  = s >> 4;
            const int c4 = (s & 15) << 2;
            float4 v = *(const float4*)&g_V[(size_t)(b * L_ + j0 + r) * DIM_ + h * HD_ + c4];
            uint4 u;
            u.x = f2tf32(v.x); u.y = f2tf32(v.y); u.z = f2tf32(v.z); u.w = f2tf32(v.w);
            *(uint4*)&KVs[r * VST + c4] = u;
        }
        __syncthreads();

        // ---- PV mma: P frags via intra-quad shuffle C->A permutation
        const int srcA = (lane & ~3) | (tg >> 1);
        const int srcB = srcA + 2;
        const bool odd = (tg & 1);
#pragma unroll
        for (int kb = 0; kb < 8; kb++) {
            float p0a = __shfl_sync(0xffffffffu, s1[kb][0], srcA);
            float p1a = __shfl_sync(0xffffffffu, s1[kb][1], srcA);
            float p2a = __shfl_sync(0xffffffffu, s1[kb][2], srcA);
            float p3a = __shfl_sync(0xffffffffu, s1[kb][3], srcA);
            float p0b = __shfl_sync(0xffffffffu, s1[kb][0], srcB);
            float p1b = __shfl_sync(0xffffffffu, s1[kb][1], srcB);
            float p2b = __shfl_sync(0xffffffffu, s1[kb][2], srcB);
            float p3b = __shfl_sync(0xffffffffu, s1[kb][3], srcB);
            uint32_t A1_0 = f2tf32(odd ? p1a : p0a);
            uint32_t A1_1 = f2tf32(odd ? p3a : p2a);
            uint32_t A1_2 = f2tf32(odd ? p1b : p0b);
            uint32_t A1_3 = f2tf32(odd ? p3b : p2b);

            p0a = __shfl_sync(0xffffffffu, s2[kb][0], srcA);
            p1a = __shfl_sync(0xffffffffu, s2[kb][1], srcA);
            p2a = __shfl_sync(0xffffffffu, s2[kb][2], srcA);
            p3a = __shfl_sync(0xffffffffu, s2[kb][3], srcA);
            p0b = __shfl_sync(0xffffffffu, s2[kb][0], srcB);
            p1b = __shfl_sync(0xffffffffu, s2[kb][1], srcB);
            p2b = __shfl_sync(0xffffffffu, s2[kb][2], srcB);
            p3b = __shfl_sync(0xffffffffu, s2[kb][3], srcB);
            uint32_t A2_0 = f2tf32(odd ? p1a : p0a);
            uint32_t A2_1 = f2tf32(odd ? p3a : p2a);
            uint32_t A2_2 = f2tf32(odd ? p1b : p0b);
            uint32_t A2_3 = f2tf32(odd ? p3b : p2b);

#pragma unroll
            for (int nb = 0; nb < 8; nb++) {
                uint32_t b0 = KVs[(kb * 8 + tg)     * VST + nb * 8 + g];
                uint32_t b1 = KVs[(kb * 8 + tg + 4) * VST + nb * 8 + g];
                mma_tf32(O1[nb][0], O1[nb][1], O1[nb][2], O1[nb][3],
                         A1_0, A1_1, A1_2, A1_3, b0, b1);
                mma_tf32(O2[nb][0], O2[nb][1], O2[nb][2], O2[nb][3],
                         A2_0, A2_1, A2_2, A2_3, b0, b1);
            }
        }
    }

    // ---- combine + write
    const float mixr = (tanhf(__ldg(mixp)) + 1.f) * 0.5f;
    const float w1g = (1.f - mixr) / l1[0], w1h = (1.f - mixr) / l1[1];
    const float w2g = mixr / l2[0],         w2h = mixr / l2[1];
    float* Ao = g_AO + (size_t)(b * L_ + i0 + wrow) * DIM_ + h * HD_;
#pragma unroll
    for (int nb = 0; nb < 8; nb++) {
        const int col = nb * 8 + 2 * tg;
        float2 o;
        o.x = O1[nb][0] * w1g + O2[nb][0] * w2g;
        o.y = O1[nb][1] * w1g + O2[nb][1] * w2g;
        *(float2*)(Ao + (size_t)g * DIM_ + col) = o;
        o.x = O1[nb][2] * w1h + O2[nb][2] * w2h;
        o.y = O1[nb][3] * w1h + O2[nb][3] * w2h;
        *(float2*)(Ao + (size_t)(g + 8) * DIM_ + col) = o;
    }
}

// ---------------------------------------------------------------------------
extern "C" void kernel_launch(void* const* d_in, const int* in_sizes, int n_in,
                              void* d_out, int out_size)
{
    const float* seq1 = (const float*)d_in[0];
    const float* seq2 = (const float*)d_in[1];
    const float* atc1 = (const float*)d_in[2];
    const float* atc2 = (const float*)d_in[3];
    const float* Wq   = (const float*)d_in[4];
    const float* bq   = (const float*)d_in[5];
    const float* Wk   = (const float*)d_in[6];
    const float* bk   = (const float*)d_in[7];
    const float* Wv   = (const float*)d_in[8];
    const float* bv   = (const float*)d_in[9];
    const float* Wo   = (const float*)d_in[10];
    const float* bo   = (const float*)d_in[11];
    const float* U    = (const float*)d_in[12];
    const float* mixp = (const float*)d_in[13];
    float* out = (float*)d_out;

    const int M = B_ * L_;                       // 4096

    // Fused Q/K/V projections
    gemm_tf32_mma<<<dim3(DIM_ / 128, M / 128, 3), 256>>>(
        seq1, seq2, Wq, bq, Wk, bk, Wv, bv, nullptr, 0);

    // Fused attention (QK^T + dual softmax + Atchley bias + mix + @V)
    attn_fused_kernel<<<dim3(L_ / 128, B_ * H_), 256>>>(atc1, atc2, U, mixp);

    // Output projection -> d_out
    gemm_tf32_mma<<<dim3(DIM_ / 128, M / 128, 1), 256>>>(
        nullptr, nullptr, Wo, bo, nullptr, nullptr, nullptr, nullptr, out, 1);
}

// round 6
// speedup vs baseline: 3.0954x; 1.1126x over previous
#include <cuda_runtime.h>
#include <math.h>
#include <cstdint>

#define B_   8
#define H_   16
#define L_   512
#define DIM_ 1024
#define HD_  64

// Scratch (device globals: allocation-free per harness rules)
__device__ float g_Q [B_ * L_ * DIM_];
__device__ float g_K [B_ * L_ * DIM_];
__device__ float g_V [B_ * L_ * DIM_];
__device__ float g_AO[B_ * L_ * DIM_];

// ===========================================================================
// tf32 helpers (baseline PTX, supported on compute_103)
// ===========================================================================
__device__ __forceinline__ uint32_t f2tf32(float f) {
    uint32_t o;
    asm("cvt.rna.tf32.f32 %0, %1;" : "=r"(o) : "f"(f));
    return o;
}

__device__ __forceinline__ void mma_tf32(
    float& d0, float& d1, float& d2, float& d3,
    uint32_t a0, uint32_t a1, uint32_t a2, uint32_t a3,
    uint32_t b0, uint32_t b1)
{
    asm volatile(
        "mma.sync.aligned.m16n8k8.row.col.f32.tf32.tf32.f32 "
        "{%0,%1,%2,%3}, {%4,%5,%6,%7}, {%8,%9}, {%0,%1,%2,%3};"
        : "+f"(d0), "+f"(d1), "+f"(d2), "+f"(d3)
        : "r"(a0), "r"(a1), "r"(a2), "r"(a3), "r"(b0), "r"(b1));
}

// ===========================================================================
// Projection GEMM v2: C[M,1024] = A[M,1024] @ W[1024,1024]^T + bias
// CTA tile 128x128, 4 warps (2m x 2n), warp tile 64x64 (mt=4, nt=8).
// KB=16, double-buffered. 1.0 LDS port-cycle per mma.
// mode 0: fused QKV (z=0 Q, z=1 K, z=2 V), mode 1: output proj -> C_ext
// ===========================================================================
#define GK    1024
#define KB    16
#define NCH   (GK / KB)
#define SST   20

__global__ __launch_bounds__(128, 2) void gemm_tf32_mma(
    const float* __restrict__ seq1, const float* __restrict__ seq2,
    const float* __restrict__ Wq, const float* __restrict__ bq,
    const float* __restrict__ Wk, const float* __restrict__ bk,
    const float* __restrict__ Wv, const float* __restrict__ bv,
    float* __restrict__ C_ext, int mode)
{
    const float* A;
    const float* W;
    const float* bias;
    float* C;
    if (mode == 1) {
        A = (const float*)g_AO; W = Wq; bias = bq; C = C_ext;
    } else {
        const int z = blockIdx.z;
        if (z == 0)      { A = seq1; W = Wq; bias = bq; C = g_Q; }
        else if (z == 1) { A = seq2; W = Wk; bias = bk; C = g_K; }
        else             { A = seq2; W = Wv; bias = bv; C = g_V; }
    }

    __shared__ uint32_t As[2][128 * SST];
    __shared__ uint32_t Bs[2][128 * SST];
    __shared__ float s_bias[128];

    const int tid  = threadIdx.x;
    const int wid  = tid >> 5;
    const int lane = tid & 31;
    const int g    = lane >> 2;
    const int tg   = lane & 3;
    const int mrow = (wid >> 1) * 64;
    const int ncol = (wid & 1) * 64;

    const float* Arow = A + (size_t)blockIdx.y * 128 * GK;
    const float* Wrow = W + (size_t)blockIdx.x * 128 * GK;

    if (tid < 128) s_bias[tid] = bias[blockIdx.x * 128 + tid];

    // global-load slots: 512 float4 per tile, 4 per thread (128 threads)
    int rL[4], kL[4];
#pragma unroll
    for (int t = 0; t < 4; t++) {
        const int s = tid + t * 128;
        rL[t] = s >> 2;
        kL[t] = (s & 3) << 2;
    }

    float acc[4][8][4];
#pragma unroll
    for (int mt = 0; mt < 4; mt++)
#pragma unroll
        for (int nt = 0; nt < 8; nt++)
#pragma unroll
            for (int e = 0; e < 4; e++) acc[mt][nt][e] = 0.f;

    // Prologue: chunk 0 -> stage 0
    {
#pragma unroll
        for (int t = 0; t < 4; t++) {
            float4 va = __ldg((const float4*)(Arow + (size_t)rL[t] * GK + kL[t]));
            float4 vb = __ldg((const float4*)(Wrow + (size_t)rL[t] * GK + kL[t]));
            uint4 u;
            u.x = f2tf32(va.x); u.y = f2tf32(va.y); u.z = f2tf32(va.z); u.w = f2tf32(va.w);
            *(uint4*)&As[0][rL[t] * SST + kL[t]] = u;
            u.x = f2tf32(vb.x); u.y = f2tf32(vb.y); u.z = f2tf32(vb.z); u.w = f2tf32(vb.w);
            *(uint4*)&Bs[0][rL[t] * SST + kL[t]] = u;
        }
    }
    __syncthreads();

    for (int i = 0; i < NCH; i++) {
        const int st = i & 1;
        float4 va[4], vb[4];
        const bool more = (i + 1 < NCH);
        if (more) {
            const int ko = (i + 1) * KB;
#pragma unroll
            for (int t = 0; t < 4; t++) {
                va[t] = __ldg((const float4*)(Arow + (size_t)rL[t] * GK + ko + kL[t]));
                vb[t] = __ldg((const float4*)(Wrow + (size_t)rL[t] * GK + ko + kL[t]));
            }
        }

#pragma unroll
        for (int ks = 0; ks < 2; ks++) {
            uint32_t a[4][4];
#pragma unroll
            for (int mt = 0; mt < 4; mt++) {
                const int rb = mrow + mt * 16 + g;
                a[mt][0] = As[st][(rb)     * SST + ks * 8 + tg];
                a[mt][1] = As[st][(rb + 8) * SST + ks * 8 + tg];
                a[mt][2] = As[st][(rb)     * SST + ks * 8 + tg + 4];
                a[mt][3] = As[st][(rb + 8) * SST + ks * 8 + tg + 4];
            }
#pragma unroll
            for (int nt = 0; nt < 8; nt++) {
                const int rw = ncol + nt * 8 + g;
                uint32_t b0 = Bs[st][rw * SST + ks * 8 + tg];
                uint32_t b1 = Bs[st][rw * SST + ks * 8 + tg + 4];
#pragma unroll
                for (int mt = 0; mt < 4; mt++)
                    mma_tf32(acc[mt][nt][0], acc[mt][nt][1], acc[mt][nt][2], acc[mt][nt][3],
                             a[mt][0], a[mt][1], a[mt][2], a[mt][3], b0, b1);
            }
        }

        if (more) {
            const int ns = st ^ 1;
            uint4 u;
#pragma unroll
            for (int t = 0; t < 4; t++) {
                u.x = f2tf32(va[t].x); u.y = f2tf32(va[t].y);
                u.z = f2tf32(va[t].z); u.w = f2tf32(va[t].w);
                *(uint4*)&As[ns][rL[t] * SST + kL[t]] = u;
                u.x = f2tf32(vb[t].x); u.y = f2tf32(vb[t].y);
                u.z = f2tf32(vb[t].z); u.w = f2tf32(vb[t].w);
                *(uint4*)&Bs[ns][rL[t] * SST + kL[t]] = u;
            }
            __syncthreads();
        }
    }

#pragma unroll
    for (int mt = 0; mt < 4; mt++) {
#pragma unroll
        for (int nt = 0; nt < 8; nt++) {
            const int row = mrow + mt * 16 + g;
            const int col = ncol + nt * 8 + 2 * tg;
            const int gm0 = blockIdx.y * 128 + row;
            const int gc  = blockIdx.x * 128 + col;
            float2 o;
            o.x = acc[mt][nt][0] + s_bias[col];
            o.y = acc[mt][nt][1] + s_bias[col + 1];
            *(float2*)(C + (size_t)gm0 * DIM_ + gc) = o;
            o.x = acc[mt][nt][2] + s_bias[col];
            o.y = acc[mt][nt][3] + s_bias[col + 1];
            *(float2*)(C + (size_t)(gm0 + 8) * DIM_ + gc) = o;
        }
    }
}

// ===========================================================================
// Fused attention (unchanged, known-passing):
// QK^T -> dual online softmax (+Atchley bias) -> mix -> @V, output -> g_AO
// ===========================================================================
#define KST 68
#define VST 72

__global__ __launch_bounds__(256) void attn_fused_kernel(
    const float* __restrict__ atc1, const float* __restrict__ atc2,
    const float* __restrict__ U, const float* __restrict__ mixp)
{
    const int bh = blockIdx.y;
    const int b  = bh >> 4;
    const int h  = bh & 15;
    const int i0 = blockIdx.x * 128;

    __shared__ uint32_t KVs[64 * VST];
    __shared__ float Atc2s[64][5];

    const int tid  = threadIdx.x;
    const int wid  = tid >> 5;
    const int lane = tid & 31;
    const int g    = lane >> 2;
    const int tg   = lane & 3;
    const int wrow = wid * 16;

    uint32_t qf[8][4];
    {
        const float* Qb = g_Q + (size_t)(b * L_ + i0 + wrow) * DIM_ + h * HD_;
#pragma unroll
        for (int kb = 0; kb < 8; kb++) {
            qf[kb][0] = f2tf32(__ldg(Qb + (size_t)g       * DIM_ + kb * 8 + tg));
            qf[kb][1] = f2tf32(__ldg(Qb + (size_t)(g + 8) * DIM_ + kb * 8 + tg));
            qf[kb][2] = f2tf32(__ldg(Qb + (size_t)g       * DIM_ + kb * 8 + tg + 4));
            qf[kb][3] = f2tf32(__ldg(Qb + (size_t)(g + 8) * DIM_ + kb * 8 + tg + 4));
        }
    }

    float a1u0[5], a1u8[5];
    {
        const float* a1p = atc1 + (size_t)(b * L_ + i0 + wrow + g) * 5;
        float a1_0[5], a1_8[5];
#pragma unroll
        for (int p = 0; p < 5; p++) {
            a1_0[p] = __ldg(a1p + p);
            a1_8[p] = __ldg(a1p + 40 + p);
        }
#pragma unroll
        for (int q = 0; q < 5; q++) {
            float s0 = 0.f, s8 = 0.f;
#pragma unroll
            for (int p = 0; p < 5; p++) {
                float u = __ldg(&U[h * 25 + p * 5 + q]);
                s0 = fmaf(a1_0[p], u, s0);
                s8 = fmaf(a1_8[p], u, s8);
            }
            a1u0[q] = s0;
            a1u8[q] = s8;
        }
    }

    float m1[2] = {-1e30f, -1e30f}, l1[2] = {0.f, 0.f};
    float m2[2] = {-1e30f, -1e30f}, l2[2] = {0.f, 0.f};
    float O1[8][4], O2[8][4];
#pragma unroll
    for (int nb = 0; nb < 8; nb++)
#pragma unroll
        for (int e = 0; e < 4; e++) { O1[nb][e] = 0.f; O2[nb][e] = 0.f; }

    for (int ch = 0; ch < 8; ch++) {
        const int j0 = ch * 64;
        __syncthreads();

#pragma unroll
        for (int t = 0; t < 4; t++) {
            const int s  = tid + t * 256;
            const int r  = s >> 4;
            const int c4 = (s & 15) << 2;
            float4 k = *(const float4*)&g_K[(size_t)(b * L_ + j0 + r) * DIM_ + h * HD_ + c4];
            uint4 u;
            u.x = f2tf32(k.x); u.y = f2tf32(k.y); u.z = f2tf32(k.z); u.w = f2tf32(k.w);
            *(uint4*)&KVs[r * KST + c4] = u;
        }
        if (tid < 64) {
#pragma unroll
            for (int q = 0; q < 5; q++)
                Atc2s[tid][q] = __ldg(&atc2[(size_t)(b * L_ + j0 + tid) * 5 + q]);
        }
        __syncthreads();

        float s1[8][4];
#pragma unroll
        for (int nt = 0; nt < 8; nt++)
#pragma unroll
            for (int e = 0; e < 4; e++) s1[nt][e] = 0.f;
#pragma unroll
        for (int kb = 0; kb < 8; kb++) {
#pragma unroll
            for (int nt = 0; nt < 8; nt++) {
                uint32_t b0 = KVs[(nt * 8 + g) * KST + kb * 8 + tg];
                uint32_t b1 = KVs[(nt * 8 + g) * KST + kb * 8 + tg + 4];
                mma_tf32(s1[nt][0], s1[nt][1], s1[nt][2], s1[nt][3],
                         qf[kb][0], qf[kb][1], qf[kb][2], qf[kb][3], b0, b1);
            }
        }
        float s2[8][4];
#pragma unroll
        for (int nt = 0; nt < 8; nt++) {
            const int c0 = nt * 8 + 2 * tg;
            float d00 = 0.f, d01 = 0.f, d80 = 0.f, d81 = 0.f;
#pragma unroll
            for (int q = 0; q < 5; q++) {
                float a20 = Atc2s[c0][q];
                float a21 = Atc2s[c0 + 1][q];
                d00 = fmaf(a1u0[q], a20, d00);
                d01 = fmaf(a1u0[q], a21, d01);
                d80 = fmaf(a1u8[q], a20, d80);
                d81 = fmaf(a1u8[q], a21, d81);
            }
            s2[nt][0] = d00; s2[nt][1] = d01; s2[nt][2] = d80; s2[nt][3] = d81;
#pragma unroll
            for (int e = 0; e < 4; e++) s1[nt][e] *= 0.125f;
        }

        float cm1g = -1e30f, cm1h = -1e30f, cm2g = -1e30f, cm2h = -1e30f;
#pragma unroll
        for (int nt = 0; nt < 8; nt++) {
            cm1g = fmaxf(cm1g, fmaxf(s1[nt][0], s1[nt][1]));
            cm1h = fmaxf(cm1h, fmaxf(s1[nt][2], s1[nt][3]));
            cm2g = fmaxf(cm2g, fmaxf(s2[nt][0], s2[nt][1]));
            cm2h = fmaxf(cm2h, fmaxf(s2[nt][2], s2[nt][3]));
        }
#pragma unroll
        for (int o = 1; o <= 2; o <<= 1) {
            cm1g = fmaxf(cm1g, __shfl_xor_sync(0xffffffffu, cm1g, o));
            cm1h = fmaxf(cm1h, __shfl_xor_sync(0xffffffffu, cm1h, o));
            cm2g = fmaxf(cm2g, __shfl_xor_sync(0xffffffffu, cm2g, o));
            cm2h = fmaxf(cm2h, __shfl_xor_sync(0xffffffffu, cm2h, o));
        }

        float nm, al;
        nm = fmaxf(m1[0], cm1g); al = __expf(m1[0] - nm); m1[0] = nm; l1[0] *= al;
#pragma unroll
        for (int nb = 0; nb < 8; nb++) { O1[nb][0] *= al; O1[nb][1] *= al; }
        nm = fmaxf(m1[1], cm1h); al = __expf(m1[1] - nm); m1[1] = nm; l1[1] *= al;
#pragma unroll
        for (int nb = 0; nb < 8; nb++) { O1[nb][2] *= al; O1[nb][3] *= al; }
        nm = fmaxf(m2[0], cm2g); al = __expf(m2[0] - nm); m2[0] = nm; l2[0] *= al;
#pragma unroll
        for (int nb = 0; nb < 8; nb++) { O2[nb][0] *= al; O2[nb][1] *= al; }
        nm = fmaxf(m2[1], cm2h); al = __expf(m2[1] - nm); m2[1] = nm; l2[1] *= al;
#pragma unroll
        for (int nb = 0; nb < 8; nb++) { O2[nb][2] *= al; O2[nb][3] *= al; }

        float rs1g = 0.f, rs1h = 0.f, rs2g = 0.f, rs2h = 0.f;
#pragma unroll
        for (int nt = 0; nt < 8; nt++) {
            s1[nt][0] = __expf(s1[nt][0] - m1[0]); rs1g += s1[nt][0];
            s1[nt][1] = __expf(s1[nt][1] - m1[0]); rs1g += s1[nt][1];
            s1[nt][2] = __expf(s1[nt][2] - m1[1]); rs1h += s1[nt][2];
            s1[nt][3] = __expf(s1[nt][3] - m1[1]); rs1h += s1[nt][3];
            s2[nt][0] = __expf(s2[nt][0] - m2[0]); rs2g += s2[nt][0];
            s2[nt][1] = __expf(s2[nt][1] - m2[0]); rs2g += s2[nt][1];
            s2[nt][2] = __expf(s2[nt][2] - m2[1]); rs2h += s2[nt][2];
            s2[nt][3] = __expf(s2[nt][3] - m2[1]); rs2h += s2[nt][3];
        }
#pragma unroll
        for (int o = 1; o <= 2; o <<= 1) {
            rs1g += __shfl_xor_sync(0xffffffffu, rs1g, o);
            rs1h += __shfl_xor_sync(0xffffffffu, rs1h, o);
            rs2g += __shfl_xor_sync(0xffffffffu, rs2g, o);
            rs2h += __shfl_xor_sync(0xffffffffu, rs2h, o);
        }
        l1[0] += rs1g; l1[1] += rs1h;
        l2[0] += rs2g; l2[1] += rs2h;

        __syncthreads();

#pragma unroll
        for (int t = 0; t < 4; t++) {
            const int s  = tid + t * 256;
            const int r  = s >> 4;
            const int c4 = (s & 15) << 2;
            float4 v = *(const float4*)&g_V[(size_t)(b * L_ + j0 + r) * DIM_ + h * HD_ + c4];
            uint4 u;
            u.x = f2tf32(v.x); u.y = f2tf32(v.y); u.z = f2tf32(v.z); u.w = f2tf32(v.w);
            *(uint4*)&KVs[r * VST + c4] = u;
        }
        __syncthreads();

        const int srcA = (lane & ~3) | (tg >> 1);
        const int srcB = srcA + 2;
        const bool odd = (tg & 1);
#pragma unroll
        for (int kb = 0; kb < 8; kb++) {
            float p0a = __shfl_sync(0xffffffffu, s1[kb][0], srcA);
            float p1a = __shfl_sync(0xffffffffu, s1[kb][1], srcA);
            float p2a = __shfl_sync(0xffffffffu, s1[kb][2], srcA);
            float p3a = __shfl_sync(0xffffffffu, s1[kb][3], srcA);
            float p0b = __shfl_sync(0xffffffffu, s1[kb][0], srcB);
            float p1b = __shfl_sync(0xffffffffu, s1[kb][1], srcB);
            float p2b = __shfl_sync(0xffffffffu, s1[kb][2], srcB);
            float p3b = __shfl_sync(0xffffffffu, s1[kb][3], srcB);
            uint32_t A1_0 = f2tf32(odd ? p1a : p0a);
            uint32_t A1_1 = f2tf32(odd ? p3a : p2a);
            uint32_t A1_2 = f2tf32(odd ? p1b : p0b);
            uint32_t A1_3 = f2tf32(odd ? p3b : p2b);

            p0a = __shfl_sync(0xffffffffu, s2[kb][0], srcA);
            p1a = __shfl_sync(0xffffffffu, s2[kb][1], srcA);
            p2a = __shfl_sync(0xffffffffu, s2[kb][2], srcA);
            p3a = __shfl_sync(0xffffffffu, s2[kb][3], srcA);
            p0b = __shfl_sync(0xffffffffu, s2[kb][0], srcB);
            p1b = __shfl_sync(0xffffffffu, s2[kb][1], srcB);
            p2b = __shfl_sync(0xffffffffu, s2[kb][2], srcB);
            p3b = __shfl_sync(0xffffffffu, s2[kb][3], srcB);
            uint32_t A2_0 = f2tf32(odd ? p1a : p0a);
            uint32_t A2_1 = f2tf32(odd ? p3a : p2a);
            uint32_t A2_2 = f2tf32(odd ? p1b : p0b);
            uint32_t A2_3 = f2tf32(odd ? p3b : p2b);

#pragma unroll
            for (int nb = 0; nb < 8; nb++) {
                uint32_t b0 = KVs[(kb * 8 + tg)     * VST + nb * 8 + g];
                uint32_t b1 = KVs[(kb * 8 + tg + 4) * VST + nb * 8 + g];
                mma_tf32(O1[nb][0], O1[nb][1], O1[nb][2], O1[nb][3],
                         A1_0, A1_1, A1_2, A1_3, b0, b1);
                mma_tf32(O2[nb][0], O2[nb][1], O2[nb][2], O2[nb][3],
                         A2_0, A2_1, A2_2, A2_3, b0, b1);
            }
        }
    }

    const float mixr = (tanhf(__ldg(mixp)) + 1.f) * 0.5f;
    const float w1g = (1.f - mixr) / l1[0], w1h = (1.f - mixr) / l1[1];
    const float w2g = mixr / l2[0],         w2h = mixr / l2[1];
    float* Ao = g_AO + (size_t)(b * L_ + i0 + wrow) * DIM_ + h * HD_;
#pragma unroll
    for (int nb = 0; nb < 8; nb++) {
        const int col = nb * 8 + 2 * tg;
        float2 o;
        o.x = O1[nb][0] * w1g + O2[nb][0] * w2g;
        o.y = O1[nb][1] * w1g + O2[nb][1] * w2g;
        *(float2*)(Ao + (size_t)g * DIM_ + col) = o;
        o.x = O1[nb][2] * w1h + O2[nb][2] * w2h;
        o.y = O1[nb][3] * w1h + O2[nb][3] * w2h;
        *(float2*)(Ao + (size_t)(g + 8) * DIM_ + col) = o;
    }
}

// ---------------------------------------------------------------------------
extern "C" void kernel_launch(void* const* d_in, const int* in_sizes, int n_in,
                              void* d_out, int out_size)
{
    const float* seq1 = (const float*)d_in[0];
    const float* seq2 = (const float*)d_in[1];
    const float* atc1 = (const float*)d_in[2];
    const float* atc2 = (const float*)d_in[3];
    const float* Wq   = (const float*)d_in[4];
    const float* bq   = (const float*)d_in[5];
    const float* Wk   = (const float*)d_in[6];
    const float* bk   = (const float*)d_in[7];
    const float* Wv   = (const float*)d_in[8];
    const float* bv   = (const float*)d_in[9];
    const float* Wo   = (const float*)d_in[10];
    const float* bo   = (const float*)d_in[11];
    const float* U    = (const float*)d_in[12];
    const float* mixp = (const float*)d_in[13];
    float* out = (float*)d_out;

    const int M = B_ * L_;                       // 4096

    // Fused Q/K/V projections (128 threads, warp tile 64x64)
    gemm_tf32_mma<<<dim3(DIM_ / 128, M / 128, 3), 128>>>(
        seq1, seq2, Wq, bq, Wk, bk, Wv, bv, nullptr, 0);

    // Fused attention (QK^T + dual softmax + Atchley bias + mix + @V)
    attn_fused_kernel<<<dim3(L_ / 128, B_ * H_), 256>>>(atc1, atc2, U, mixp);

    // Output projection -> d_out
    gemm_tf32_mma<<<dim3(DIM_ / 128, M / 128, 1), 128>>>(
        nullptr, nullptr, Wo, bo, nullptr, nullptr, nullptr, nullptr, out, 1);
}